// round 2
// baseline (speedup 1.0000x reference)
#include <cuda_runtime.h>

#define EMAX 800000
#define K1DIM 128   // 2H
#define C1 256      // 4H
#define C2 64       // H
#define EPSV 1e-5f

// -------- scratch (static device arrays; no runtime allocation) ----------
__device__ float g_Y1[(size_t)EMAX * C1];   // layer-1 pre-norm output
__device__ float g_Y2[(size_t)EMAX * C2];   // layer-2 pre-norm output
__device__ float g_s1[2 * C1];              // sum, sumsq for layer 1
__device__ float g_mr1[2 * C1];             // mean, rstd for layer 1
__device__ float g_s2[2 * C2];
__device__ float g_mr2[2 * C2];
__device__ int   g_idx64;                   // 1 if edge_index is int64

// -------- pre: zero stats + detect index dtype ---------------------------
__global__ void k_pre(const int* __restrict__ ei_words)
{
    int gid = blockIdx.x * blockDim.x + threadIdx.x;
    if (gid == 0) {
        // If edge_index is int64 (indices < 2^31), every odd 32-bit word is 0.
        // If int32, odd words are random values in [0, 50000): P(all zero) ~ 0.
        int orv = 0;
        #pragma unroll
        for (int i = 1; i < 32; i += 2) orv |= ei_words[i];
        g_idx64 = (orv == 0) ? 1 : 0;
    }
    if (gid < 2 * C1) g_s1[gid] = 0.0f;
    if (gid < 2 * C2) g_s2[gid] = 0.0f;
}

// -------- layer 1: gather-concat GEMM + channel stats --------------------
// Persistent CTAs. smem: W1 [128][256] (128KB) + A tile [32][128] (16KB).
// 256 threads: tx = tid&31 -> 8 cols, ty = tid>>5 -> 4 rows. 32 acc/thread.
__global__ __launch_bounds__(256, 1)
void k_gemm1(const float* __restrict__ emb,
             const void* __restrict__ ei,
             const float* __restrict__ W1,
             const float* __restrict__ b1,
             int E)
{
    extern __shared__ float sm[];
    float* Ws = sm;                 // 128*256
    float* As = sm + K1DIM * C1;    // 32*128

    const int tid = threadIdx.x;
    for (int i = tid; i < K1DIM * C1 / 4; i += blockDim.x)
        ((float4*)Ws)[i] = ((const float4*)W1)[i];

    const long long* ei64 = (const long long*)ei;
    const int*       ei32 = (const int*)ei;
    const int is64 = g_idx64;

    const int tx = tid & 31;   // col group: cols [tx*8, tx*8+8)
    const int ty = tid >> 5;   // row group: rows [ty*4, ty*4+4)

    float biasReg[8];
    #pragma unroll
    for (int c = 0; c < 8; c++) biasReg[c] = b1[tx * 8 + c];

    float rSum[8], rSq[8];
    #pragma unroll
    for (int c = 0; c < 8; c++) { rSum[c] = 0.0f; rSq[c] = 0.0f; }

    __syncthreads();

    const int nTiles = (E + 31) / 32;
    for (int tile = blockIdx.x; tile < nTiles; tile += gridDim.x) {
        const int base = tile * 32;

        // gather: 32 rows x 128 floats (= 32 float4 per row), coalesced
        for (int i = tid; i < 32 * 32; i += blockDim.x) {
            const int r = i >> 5, q = i & 31;
            const int e = base + r;
            float4 v = make_float4(0.f, 0.f, 0.f, 0.f);
            if (e < E) {
                long long src;
                if (q < 16) src = is64 ? ei64[e]     : (long long)ei32[e];
                else        src = is64 ? ei64[E + e] : (long long)ei32[E + e];
                v = *(const float4*)(emb + src * 64 + (q & 15) * 4);
            }
            ((float4*)(As + r * K1DIM))[q] = v;
        }
        __syncthreads();

        float acc[4][8];
        #pragma unroll
        for (int r = 0; r < 4; r++)
            #pragma unroll
            for (int c = 0; c < 8; c++) acc[r][c] = 0.0f;

        const float* Arow = As + (ty * 4) * K1DIM;
        #pragma unroll 4
        for (int k = 0; k < K1DIM; k++) {
            const float4 w0 = *((const float4*)(Ws + k * C1 + tx * 8));
            const float4 w1 = *((const float4*)(Ws + k * C1 + tx * 8 + 4));
            const float a0 = Arow[k];
            const float a1 = Arow[K1DIM + k];
            const float a2 = Arow[2 * K1DIM + k];
            const float a3 = Arow[3 * K1DIM + k];
            #define FMA8(r, a)                                            \
                acc[r][0] += (a) * w0.x; acc[r][1] += (a) * w0.y;         \
                acc[r][2] += (a) * w0.z; acc[r][3] += (a) * w0.w;         \
                acc[r][4] += (a) * w1.x; acc[r][5] += (a) * w1.y;         \
                acc[r][6] += (a) * w1.z; acc[r][7] += (a) * w1.w;
            FMA8(0, a0) FMA8(1, a1) FMA8(2, a2) FMA8(3, a3)
            #undef FMA8
        }

        #pragma unroll
        for (int r = 0; r < 4; r++) {
            const int e = base + ty * 4 + r;
            if (e < E) {
                float v[8];
                #pragma unroll
                for (int c = 0; c < 8; c++) {
                    v[c] = acc[r][c] + biasReg[c];
                    rSum[c] += v[c];
                    rSq[c]  += v[c] * v[c];
                }
                float4* dst = (float4*)(g_Y1 + (size_t)e * C1 + tx * 8);
                dst[0] = make_float4(v[0], v[1], v[2], v[3]);
                dst[1] = make_float4(v[4], v[5], v[6], v[7]);
            }
        }
        __syncthreads();
    }

    // block reduce per-channel partial sums (8 ty groups), then global atomics
    float* redS = sm;            // [8][256]
    float* redQ = sm + 8 * C1;   // [8][256]
    __syncthreads();
    #pragma unroll
    for (int c = 0; c < 8; c++) {
        redS[ty * C1 + tx * 8 + c] = rSum[c];
        redQ[ty * C1 + tx * 8 + c] = rSq[c];
    }
    __syncthreads();
    if (tid < C1) {
        float s = 0.f, q = 0.f;
        #pragma unroll
        for (int g = 0; g < 8; g++) { s += redS[g * C1 + tid]; q += redQ[g * C1 + tid]; }
        atomicAdd(&g_s1[tid], s);
        atomicAdd(&g_s1[C1 + tid], q);
    }
}

__global__ void k_fin1(float invE)
{
    const int c = threadIdx.x;
    if (c < C1) {
        const float m   = g_s1[c] * invE;
        const float var = g_s1[C1 + c] * invE - m * m;
        g_mr1[c]      = m;
        g_mr1[C1 + c] = rsqrtf(var + EPSV);
    }
}

// -------- layer 2: norm+relu(Y1) @ W2 + stats ----------------------------
// smem: W2 [256][64] (64KB) + A tile [64][260] (66.6KB) + mean/rstd (2KB).
// 256 threads: tx = tid&15 -> 4 cols, ty = tid>>4 -> 4 rows. 16 acc/thread.
#define A2S 260
__global__ __launch_bounds__(256, 1)
void k_gemm2(const float* __restrict__ W2,
             const float* __restrict__ b2,
             int E)
{
    extern __shared__ float sm[];
    float* Ws = sm;                       // 256*64
    float* As = Ws + C1 * C2;             // 64*260
    float* Ms = As + 64 * A2S;            // 256 means
    float* Rs = Ms + C1;                  // 256 rstds

    const int tid = threadIdx.x;
    for (int i = tid; i < C1 * C2 / 4; i += blockDim.x)
        ((float4*)Ws)[i] = ((const float4*)W2)[i];
    for (int i = tid; i < C1; i += blockDim.x) {
        Ms[i] = g_mr1[i];
        Rs[i] = g_mr1[C1 + i];
    }

    const int tx = tid & 15;   // cols [tx*4, tx*4+4)
    const int ty = tid >> 4;   // rows [ty*4, ty*4+4)

    float biasReg[4];
    #pragma unroll
    for (int c = 0; c < 4; c++) biasReg[c] = b2[tx * 4 + c];

    float rSum[4] = {0.f, 0.f, 0.f, 0.f};
    float rSq[4]  = {0.f, 0.f, 0.f, 0.f};

    __syncthreads();

    const int nTiles = (E + 63) / 64;
    for (int tile = blockIdx.x; tile < nTiles; tile += gridDim.x) {
        const int base = tile * 64;

        // load + normalize + relu Y1 tile: 64 rows x 64 float4
        for (int i = tid; i < 64 * 64; i += blockDim.x) {
            const int r = i >> 6, q = i & 63;
            const int e = base + r;
            float4 v = make_float4(0.f, 0.f, 0.f, 0.f);
            if (e < E) v = ((const float4*)(g_Y1 + (size_t)e * C1))[q];
            const int c0 = q * 4;
            v.x = fmaxf(0.f, (v.x - Ms[c0 + 0]) * Rs[c0 + 0]);
            v.y = fmaxf(0.f, (v.y - Ms[c0 + 1]) * Rs[c0 + 1]);
            v.z = fmaxf(0.f, (v.z - Ms[c0 + 2]) * Rs[c0 + 2]);
            v.w = fmaxf(0.f, (v.w - Ms[c0 + 3]) * Rs[c0 + 3]);
            ((float4*)(As + r * A2S))[q] = v;
        }
        __syncthreads();

        float acc[4][4];
        #pragma unroll
        for (int r = 0; r < 4; r++)
            #pragma unroll
            for (int c = 0; c < 4; c++) acc[r][c] = 0.0f;

        const float* Arow = As + (ty * 4) * A2S;
        #pragma unroll 4
        for (int k = 0; k < C1; k++) {
            const float4 w = *((const float4*)(Ws + k * C2 + tx * 4));
            const float a0 = Arow[k];
            const float a1 = Arow[A2S + k];
            const float a2 = Arow[2 * A2S + k];
            const float a3 = Arow[3 * A2S + k];
            acc[0][0] += a0 * w.x; acc[0][1] += a0 * w.y; acc[0][2] += a0 * w.z; acc[0][3] += a0 * w.w;
            acc[1][0] += a1 * w.x; acc[1][1] += a1 * w.y; acc[1][2] += a1 * w.z; acc[1][3] += a1 * w.w;
            acc[2][0] += a2 * w.x; acc[2][1] += a2 * w.y; acc[2][2] += a2 * w.z; acc[2][3] += a2 * w.w;
            acc[3][0] += a3 * w.x; acc[3][1] += a3 * w.y; acc[3][2] += a3 * w.z; acc[3][3] += a3 * w.w;
        }

        #pragma unroll
        for (int r = 0; r < 4; r++) {
            const int e = base + ty * 4 + r;
            if (e < E) {
                float v[4];
                #pragma unroll
                for (int c = 0; c < 4; c++) {
                    v[c] = acc[r][c] + biasReg[c];
                    rSum[c] += v[c];
                    rSq[c]  += v[c] * v[c];
                }
                *((float4*)(g_Y2 + (size_t)e * C2 + tx * 4)) =
                    make_float4(v[0], v[1], v[2], v[3]);
            }
        }
        __syncthreads();
    }

    // block reduce (16 ty groups x 64 cols), then global atomics
    float* redS = sm;             // [16][64]
    float* redQ = sm + 16 * C2;   // [16][64]
    __syncthreads();
    #pragma unroll
    for (int c = 0; c < 4; c++) {
        redS[ty * C2 + tx * 4 + c] = rSum[c];
        redQ[ty * C2 + tx * 4 + c] = rSq[c];
    }
    __syncthreads();
    if (tid < C2) {
        float s = 0.f, q = 0.f;
        #pragma unroll
        for (int g = 0; g < 16; g++) { s += redS[g * C2 + tid]; q += redQ[g * C2 + tid]; }
        atomicAdd(&g_s2[tid], s);
        atomicAdd(&g_s2[C2 + tid], q);
    }
}

__global__ void k_fin2(float invE)
{
    const int c = threadIdx.x;
    if (c < C2) {
        const float m   = g_s2[c] * invE;
        const float var = g_s2[C2 + c] * invE - m * m;
        g_mr2[c]      = m;
        g_mr2[C2 + c] = rsqrtf(var + EPSV);
    }
}

// -------- layer 3: norm+relu(Y2) @ W3 + b3 -------------------------------
// warp per edge row, float2 per lane, shuffle reduce.
__global__ void k_out(const float* __restrict__ W3,
                      const float* __restrict__ b3,
                      float* __restrict__ out,
                      int E)
{
    __shared__ float w[C2], m[C2], rs[C2];
    const int tid = threadIdx.x;
    if (tid < C2) {
        w[tid]  = W3[tid];
        m[tid]  = g_mr2[tid];
        rs[tid] = g_mr2[C2 + tid];
    }
    __syncthreads();

    const int lane = tid & 31;
    const int warp = tid >> 5;
    const int e = blockIdx.x * (blockDim.x >> 5) + warp;
    if (e >= E) return;

    const float2 y = ((const float2*)(g_Y2 + (size_t)e * C2))[lane];
    const int c = lane * 2;
    float p = fmaxf(0.f, (y.x - m[c])     * rs[c])     * w[c]
            + fmaxf(0.f, (y.y - m[c + 1]) * rs[c + 1]) * w[c + 1];
    #pragma unroll
    for (int o = 16; o > 0; o >>= 1) p += __shfl_down_sync(0xffffffffu, p, o);
    if (lane == 0) out[e] = p + b3[0];
}

// -------- launch ----------------------------------------------------------
extern "C" void kernel_launch(void* const* d_in, const int* in_sizes, int n_in,
                              void* d_out, int out_size)
{
    const float* emb = (const float*)d_in[0];
    const void*  ei  = d_in[1];
    const float* W1  = (const float*)d_in[2];
    const float* b1  = (const float*)d_in[3];
    const float* W2  = (const float*)d_in[4];
    const float* b2  = (const float*)d_in[5];
    const float* W3  = (const float*)d_in[6];
    const float* b3  = (const float*)d_in[7];
    float* out = (float*)d_out;

    const int E = in_sizes[1] / 2;

    int dev = 0;
    cudaGetDevice(&dev);
    int nsm = 148;
    cudaDeviceGetAttribute(&nsm, cudaDevAttrMultiProcessorCount, dev);

    const int sm1 = (K1DIM * C1 + 32 * K1DIM) * (int)sizeof(float);      // 147456
    const int sm2 = (C1 * C2 + 64 * A2S + 2 * C1) * (int)sizeof(float);  // 134144
    cudaFuncSetAttribute(k_gemm1, cudaFuncAttributeMaxDynamicSharedMemorySize, sm1);
    cudaFuncSetAttribute(k_gemm2, cudaFuncAttributeMaxDynamicSharedMemorySize, sm2);

    k_pre<<<2, 256>>>((const int*)ei);
    k_gemm1<<<nsm, 256, sm1>>>(emb, ei, W1, b1, E);
    k_fin1<<<1, 256>>>(1.0f / (float)E);
    k_gemm2<<<nsm, 256, sm2>>>(W2, b2, E);
    k_fin2<<<1, 64>>>(1.0f / (float)E);
    k_out<<<(E + 7) / 8, 256>>>(W3, b3, out, E);
}

// round 3
// speedup vs baseline: 2.5668x; 2.5668x over previous
#include <cuda_runtime.h>

#define NMAX 65536
#define EMAX 800000
#define K1DIM 128   // 2H
#define C1 256      // 4H
#define C2 64       // H
#define H  64
#define EPSV 1e-5f

// -------- scratch (static device arrays; no runtime allocation) ----------
__device__ float g_Pt[(size_t)NMAX * C1];   // emb @ W1[0:64]  + b1  (per node)
__device__ float g_Pb[(size_t)NMAX * C1];   // emb @ W1[64:128]      (per node)
__device__ float g_Y2[(size_t)EMAX * C2];   // layer-2 pre-norm output
__device__ float g_s1[2 * C1];              // sum, sumsq for layer 1
__device__ float g_mr1[2 * C1];             // mean, rstd for layer 1
__device__ float g_s2[2 * C2];
__device__ float g_mr2[2 * C2];
__device__ int   g_idx64;                   // 1 if edge_index is int64

// -------- pre: zero stats + detect index dtype ---------------------------
__global__ void k_pre(const int* __restrict__ ei_words)
{
    int gid = blockIdx.x * blockDim.x + threadIdx.x;
    if (gid == 0) {
        // int64 indices < 2^31 -> every odd 32-bit word is 0.
        int orv = 0;
        #pragma unroll
        for (int i = 1; i < 32; i += 2) orv |= ei_words[i];
        g_idx64 = (orv == 0) ? 1 : 0;
    }
    if (gid < 2 * C1) g_s1[gid] = 0.0f;
    if (gid < 2 * C2) g_s2[gid] = 0.0f;
}

// -------- node projection: Pt = emb @ W1_top + b1 ; Pb = emb @ W1_bot ----
// Persistent CTAs. smem: W1 [128][256] (128KB) + emb tile [32][64] (8KB).
// 256 threads: tx = tid&31 -> 8 cols, ty = tid>>5 -> 4 rows.
__global__ __launch_bounds__(256, 1)
void k_proj(const float* __restrict__ emb,
            const float* __restrict__ W1,
            const float* __restrict__ b1,
            int N)
{
    extern __shared__ float sm[];
    float* Ws = sm;                 // 128*256
    float* As = sm + K1DIM * C1;    // 32*64

    const int tid = threadIdx.x;
    for (int i = tid; i < K1DIM * C1 / 4; i += blockDim.x)
        ((float4*)Ws)[i] = ((const float4*)W1)[i];

    const int tx = tid & 31;   // cols [tx*8, tx*8+8)
    const int ty = tid >> 5;   // rows [ty*4, ty*4+4)

    float biasReg[8];
    #pragma unroll
    for (int c = 0; c < 8; c++) biasReg[c] = b1[tx * 8 + c];

    __syncthreads();

    const int nTiles = (N + 31) / 32;
    for (int tile = blockIdx.x; tile < nTiles; tile += gridDim.x) {
        const int base = tile * 32;

        // load emb tile: 32 rows x 16 float4
        for (int i = tid; i < 32 * 16; i += blockDim.x) {
            const int r = i >> 4, q = i & 15;
            const int n = base + r;
            float4 v = make_float4(0.f, 0.f, 0.f, 0.f);
            if (n < N) v = ((const float4*)(emb + (size_t)n * H))[q];
            ((float4*)(As + r * H))[q] = v;
        }
        __syncthreads();

        const float* Arow = As + (ty * 4) * H;

        #define PROJ_PASS(ROWOFF, DST, ADDBIAS)                               \
        {                                                                     \
            float acc[4][8];                                                  \
            _Pragma("unroll")                                                 \
            for (int r = 0; r < 4; r++)                                       \
                _Pragma("unroll")                                             \
                for (int c = 0; c < 8; c++) acc[r][c] = 0.0f;                 \
            _Pragma("unroll 4")                                               \
            for (int k = 0; k < H; k++) {                                     \
                const float4 w0 = *((const float4*)(Ws + (ROWOFF + k) * C1 + tx * 8));     \
                const float4 w1 = *((const float4*)(Ws + (ROWOFF + k) * C1 + tx * 8 + 4)); \
                const float a0 = Arow[k];                                     \
                const float a1 = Arow[H + k];                                 \
                const float a2 = Arow[2 * H + k];                             \
                const float a3 = Arow[3 * H + k];                             \
                _Pragma("unroll")                                             \
                for (int r = 0; r < 4; r++) {                                 \
                    const float a = (r == 0) ? a0 : (r == 1) ? a1 : (r == 2) ? a2 : a3; \
                    acc[r][0] += a * w0.x; acc[r][1] += a * w0.y;             \
                    acc[r][2] += a * w0.z; acc[r][3] += a * w0.w;             \
                    acc[r][4] += a * w1.x; acc[r][5] += a * w1.y;             \
                    acc[r][6] += a * w1.z; acc[r][7] += a * w1.w;             \
                }                                                             \
            }                                                                 \
            _Pragma("unroll")                                                 \
            for (int r = 0; r < 4; r++) {                                     \
                const int n = base + ty * 4 + r;                              \
                if (n < N) {                                                  \
                    float v[8];                                               \
                    _Pragma("unroll")                                         \
                    for (int c = 0; c < 8; c++)                               \
                        v[c] = acc[r][c] + (ADDBIAS ? biasReg[c] : 0.0f);     \
                    float4* dst = (float4*)(DST + (size_t)n * C1 + tx * 8);   \
                    dst[0] = make_float4(v[0], v[1], v[2], v[3]);             \
                    dst[1] = make_float4(v[4], v[5], v[6], v[7]);             \
                }                                                             \
            }                                                                 \
        }

        PROJ_PASS(0,  g_Pt, 1)
        PROJ_PASS(64, g_Pb, 0)
        #undef PROJ_PASS

        __syncthreads();
    }
}

// -------- layer-1 stats: per-channel sum/sumsq of Pt[col]+Pb[row] --------
// One channel per thread; CTA strides edges. Coalesced 1KB row reads
// (L2-resident: Pt+Pb = 102MB < 126MB L2).
__global__ __launch_bounds__(256)
void k_stats1(const void* __restrict__ ei, int E)
{
    const long long* ei64 = (const long long*)ei;
    const int*       ei32 = (const int*)ei;
    const int is64 = g_idx64;
    const int c = threadIdx.x;

    float s = 0.0f, q = 0.0f;
    for (int e = blockIdx.x; e < E; e += gridDim.x) {
        const long long col = is64 ? ei64[e]     : (long long)ei32[e];
        const long long row = is64 ? ei64[E + e] : (long long)ei32[E + e];
        const float v = g_Pt[col * C1 + c] + g_Pb[row * C1 + c];
        s += v;
        q += v * v;
    }
    atomicAdd(&g_s1[c], s);
    atomicAdd(&g_s1[C1 + c], q);
}

__global__ void k_fin1(float invE)
{
    const int c = threadIdx.x;
    if (c < C1) {
        const float m   = g_s1[c] * invE;
        const float var = g_s1[C1 + c] * invE - m * m;
        g_mr1[c]      = m;
        g_mr1[C1 + c] = rsqrtf(var + EPSV);
    }
}

// -------- layer 2 (fused): gather Pt/Pb, norm+relu, @ W2, stats ----------
// smem: W2 [256][64] (64KB) + A tile [128][260] (133KB) + mean/rstd (2KB).
// 256 threads: tx = tid&15 -> 4 cols, ty = tid>>4 -> 8 rows. 32 acc/thread.
#define A2S 260
__global__ __launch_bounds__(256, 1)
void k_gemm2(const void* __restrict__ ei,
             const float* __restrict__ W2,
             const float* __restrict__ b2,
             int E)
{
    extern __shared__ float sm[];
    float* Ws = sm;                       // 256*64   = 16384 floats
    float* As = Ws + C1 * C2;             // 128*260  = 33280 floats
    float* Ms = As + 128 * A2S;           // 256 means (16B aligned)
    float* Rs = Ms + C1;                  // 256 rstds

    const int tid = threadIdx.x;
    for (int i = tid; i < C1 * C2 / 4; i += blockDim.x)
        ((float4*)Ws)[i] = ((const float4*)W2)[i];
    for (int i = tid; i < C1; i += blockDim.x) {
        Ms[i] = g_mr1[i];
        Rs[i] = g_mr1[C1 + i];
    }

    const long long* ei64 = (const long long*)ei;
    const int*       ei32 = (const int*)ei;
    const int is64 = g_idx64;

    const int tx = tid & 15;   // cols [tx*4, tx*4+4)
    const int ty = tid >> 4;   // rows [ty*8, ty*8+8)

    float biasReg[4];
    #pragma unroll
    for (int c = 0; c < 4; c++) biasReg[c] = b2[tx * 4 + c];

    float rSum[4] = {0.f, 0.f, 0.f, 0.f};
    float rSq[4]  = {0.f, 0.f, 0.f, 0.f};

    __syncthreads();

    const int nTiles = (E + 127) / 128;
    for (int tile = blockIdx.x; tile < nTiles; tile += gridDim.x) {
        const int base = tile * 128;

        // build A tile: 128 rows x 64 float4; Y1 recomputed on the fly
        for (int i = tid; i < 128 * 64; i += blockDim.x) {
            const int r = i >> 6, q = i & 63;
            const int e = base + r;
            float4 v = make_float4(0.f, 0.f, 0.f, 0.f);
            if (e < E) {
                const long long col = is64 ? ei64[e]     : (long long)ei32[e];
                const long long row = is64 ? ei64[E + e] : (long long)ei32[E + e];
                const float4 a  = ((const float4*)(g_Pt + col * C1))[q];
                const float4 b  = ((const float4*)(g_Pb + row * C1))[q];
                const float4 ms = ((const float4*)Ms)[q];
                const float4 rs = ((const float4*)Rs)[q];
                v.x = fmaxf(0.f, (a.x + b.x - ms.x) * rs.x);
                v.y = fmaxf(0.f, (a.y + b.y - ms.y) * rs.y);
                v.z = fmaxf(0.f, (a.z + b.z - ms.z) * rs.z);
                v.w = fmaxf(0.f, (a.w + b.w - ms.w) * rs.w);
            }
            ((float4*)(As + r * A2S))[q] = v;
        }
        __syncthreads();

        float acc[8][4];
        #pragma unroll
        for (int r = 0; r < 8; r++)
            #pragma unroll
            for (int c = 0; c < 4; c++) acc[r][c] = 0.0f;

        const float* Arow = As + (ty * 8) * A2S;
        #pragma unroll 4
        for (int k = 0; k < C1; k++) {
            const float4 w = *((const float4*)(Ws + k * C2 + tx * 4));
            float a[8];
            #pragma unroll
            for (int j = 0; j < 8; j++) a[j] = Arow[j * A2S + k];
            #pragma unroll
            for (int j = 0; j < 8; j++) {
                acc[j][0] += a[j] * w.x;
                acc[j][1] += a[j] * w.y;
                acc[j][2] += a[j] * w.z;
                acc[j][3] += a[j] * w.w;
            }
        }

        #pragma unroll
        for (int j = 0; j < 8; j++) {
            const int e = base + ty * 8 + j;
            if (e < E) {
                float v[4];
                #pragma unroll
                for (int c = 0; c < 4; c++) {
                    v[c] = acc[j][c] + biasReg[c];
                    rSum[c] += v[c];
                    rSq[c]  += v[c] * v[c];
                }
                *((float4*)(g_Y2 + (size_t)e * C2 + tx * 4)) =
                    make_float4(v[0], v[1], v[2], v[3]);
            }
        }
        __syncthreads();
    }

    // block reduce stats (16 ty groups x 64 cols), then global atomics
    float* redS = As;             // [16][64]
    float* redQ = As + 16 * C2;   // [16][64]
    __syncthreads();
    #pragma unroll
    for (int c = 0; c < 4; c++) {
        redS[ty * C2 + tx * 4 + c] = rSum[c];
        redQ[ty * C2 + tx * 4 + c] = rSq[c];
    }
    __syncthreads();
    if (tid < C2) {
        float s = 0.f, q = 0.f;
        #pragma unroll
        for (int g = 0; g < 16; g++) { s += redS[g * C2 + tid]; q += redQ[g * C2 + tid]; }
        atomicAdd(&g_s2[tid], s);
        atomicAdd(&g_s2[C2 + tid], q);
    }
}

__global__ void k_fin2(float invE)
{
    const int c = threadIdx.x;
    if (c < C2) {
        const float m   = g_s2[c] * invE;
        const float var = g_s2[C2 + c] * invE - m * m;
        g_mr2[c]      = m;
        g_mr2[C2 + c] = rsqrtf(var + EPSV);
    }
}

// -------- layer 3: norm+relu(Y2) @ W3 + b3 -------------------------------
__global__ void k_out(const float* __restrict__ W3,
                      const float* __restrict__ b3,
                      float* __restrict__ out,
                      int E)
{
    __shared__ float w[C2], m[C2], rs[C2];
    const int tid = threadIdx.x;
    if (tid < C2) {
        w[tid]  = W3[tid];
        m[tid]  = g_mr2[tid];
        rs[tid] = g_mr2[C2 + tid];
    }
    __syncthreads();

    const int lane = tid & 31;
    const int warp = tid >> 5;
    const int e = blockIdx.x * (blockDim.x >> 5) + warp;
    if (e >= E) return;

    const float2 y = ((const float2*)(g_Y2 + (size_t)e * C2))[lane];
    const int c = lane * 2;
    float p = fmaxf(0.f, (y.x - m[c])     * rs[c])     * w[c]
            + fmaxf(0.f, (y.y - m[c + 1]) * rs[c + 1]) * w[c + 1];
    #pragma unroll
    for (int o = 16; o > 0; o >>= 1) p += __shfl_down_sync(0xffffffffu, p, o);
    if (lane == 0) out[e] = p + b3[0];
}

// -------- launch ----------------------------------------------------------
extern "C" void kernel_launch(void* const* d_in, const int* in_sizes, int n_in,
                              void* d_out, int out_size)
{
    const float* emb = (const float*)d_in[0];
    const void*  ei  = d_in[1];
    const float* W1  = (const float*)d_in[2];
    const float* b1  = (const float*)d_in[3];
    const float* W2  = (const float*)d_in[4];
    const float* b2  = (const float*)d_in[5];
    const float* W3  = (const float*)d_in[6];
    const float* b3  = (const float*)d_in[7];
    float* out = (float*)d_out;

    const int N = in_sizes[0] / H;
    const int E = in_sizes[1] / 2;

    int dev = 0;
    cudaGetDevice(&dev);
    int nsm = 148;
    cudaDeviceGetAttribute(&nsm, cudaDevAttrMultiProcessorCount, dev);

    const int smP = (K1DIM * C1 + 32 * H) * (int)sizeof(float);                 // 139264
    const int sm2 = (C1 * C2 + 128 * A2S + 2 * C1) * (int)sizeof(float);        // 200704
    cudaFuncSetAttribute(k_proj,  cudaFuncAttributeMaxDynamicSharedMemorySize, smP);
    cudaFuncSetAttribute(k_gemm2, cudaFuncAttributeMaxDynamicSharedMemorySize, sm2);

    k_pre<<<2, 256>>>((const int*)ei);
    k_proj<<<nsm, 256, smP>>>(emb, W1, b1, N);
    k_stats1<<<nsm * 8, 256>>>(ei, E);
    k_fin1<<<1, 256>>>(1.0f / (float)E);
    k_gemm2<<<nsm, 256, sm2>>>(ei, W2, b2, E);
    k_fin2<<<1, 64>>>(1.0f / (float)E);
    k_out<<<(E + 7) / 8, 256>>>(W3, b3, out, E);
}

// round 5
// speedup vs baseline: 2.6683x; 1.0396x over previous
#include <cuda_runtime.h>
#include <cuda_bf16.h>
#include <cstdint>

#define NMAX 65536
#define EMAX 800000
#define K1DIM 128   // 2H
#define C1 256      // 4H
#define C2 64       // H
#define H  64
#define EPSV 1e-5f

// ---- warp MMA helpers (plain sm_103-compatible: no tcgen05) -------------
__device__ __forceinline__ uint32_t smem_u32(const void* p) {
    uint32_t a;
    asm("{ .reg .u64 t; cvta.to.shared.u64 t, %1; cvt.u32.u64 %0, t; }"
        : "=r"(a) : "l"(p));
    return a;
}
__device__ __forceinline__ void ldsm_x4(uint32_t& r0, uint32_t& r1,
                                        uint32_t& r2, uint32_t& r3, uint32_t addr) {
    asm volatile("ldmatrix.sync.aligned.m8n8.x4.shared.b16 {%0,%1,%2,%3}, [%4];"
                 : "=r"(r0), "=r"(r1), "=r"(r2), "=r"(r3) : "r"(addr));
}
__device__ __forceinline__ void ldsm_x4_t(uint32_t& r0, uint32_t& r1,
                                          uint32_t& r2, uint32_t& r3, uint32_t addr) {
    asm volatile("ldmatrix.sync.aligned.m8n8.x4.trans.shared.b16 {%0,%1,%2,%3}, [%4];"
                 : "=r"(r0), "=r"(r1), "=r"(r2), "=r"(r3) : "r"(addr));
}
__device__ __forceinline__ void mma16816(float* d,
                                         uint32_t a0, uint32_t a1, uint32_t a2, uint32_t a3,
                                         uint32_t b0, uint32_t b1) {
    asm volatile("mma.sync.aligned.m16n8k16.row.col.f32.bf16.bf16.f32 "
                 "{%0,%1,%2,%3}, {%4,%5,%6,%7}, {%8,%9}, {%0,%1,%2,%3};"
                 : "+f"(d[0]), "+f"(d[1]), "+f"(d[2]), "+f"(d[3])
                 : "r"(a0), "r"(a1), "r"(a2), "r"(a3), "r"(b0), "r"(b1));
}

// ================= scratch =================
__device__ float g_Pt[(size_t)NMAX * C1];
__device__ float g_Pb[(size_t)NMAX * C1];
__device__ float g_Y2[(size_t)EMAX * C2];
__device__ float g_s1[2 * C1];
__device__ float g_mr1[2 * C1];
__device__ float g_s2[2 * C2];
__device__ float g_mr2[2 * C2];
__device__ int   g_idx64;

// ================= pre =================
__global__ void k_pre(const int* __restrict__ ei_words)
{
    int gid = blockIdx.x * blockDim.x + threadIdx.x;
    if (gid == 0) {
        int orv = 0;
        #pragma unroll
        for (int i = 1; i < 32; i += 2) orv |= ei_words[i];
        g_idx64 = (orv == 0) ? 1 : 0;
    }
    if (gid < 2 * C1) g_s1[gid] = 0.0f;
    if (gid < 2 * C2) g_s2[gid] = 0.0f;
}

// ================= node projection (fp32 SIMT; small) =================
__global__ __launch_bounds__(256, 1)
void k_proj(const float* __restrict__ emb,
            const float* __restrict__ W1,
            const float* __restrict__ b1,
            int N)
{
    extern __shared__ float sm[];
    float* Ws = sm;                 // 128*256
    float* As = sm + K1DIM * C1;    // 32*64

    const int tid = threadIdx.x;
    for (int i = tid; i < K1DIM * C1 / 4; i += blockDim.x)
        ((float4*)Ws)[i] = ((const float4*)W1)[i];

    const int tx = tid & 31;
    const int ty = tid >> 5;

    float biasReg[8];
    #pragma unroll
    for (int c = 0; c < 8; c++) biasReg[c] = b1[tx * 8 + c];

    __syncthreads();

    const int nTiles = (N + 31) / 32;
    for (int tile = blockIdx.x; tile < nTiles; tile += gridDim.x) {
        const int base = tile * 32;
        for (int i = tid; i < 32 * 16; i += blockDim.x) {
            const int r = i >> 4, q = i & 15;
            const int n = base + r;
            float4 v = make_float4(0.f, 0.f, 0.f, 0.f);
            if (n < N) v = ((const float4*)(emb + (size_t)n * H))[q];
            ((float4*)(As + r * H))[q] = v;
        }
        __syncthreads();

        const float* Arow = As + (ty * 4) * H;

        #define PROJ_PASS(ROWOFF, DST, ADDBIAS)                               \
        {                                                                     \
            float acc[4][8];                                                  \
            _Pragma("unroll")                                                 \
            for (int r = 0; r < 4; r++)                                       \
                _Pragma("unroll")                                             \
                for (int c = 0; c < 8; c++) acc[r][c] = 0.0f;                 \
            _Pragma("unroll 4")                                               \
            for (int k = 0; k < H; k++) {                                     \
                const float4 w0 = *((const float4*)(Ws + (ROWOFF + k) * C1 + tx * 8));     \
                const float4 w1 = *((const float4*)(Ws + (ROWOFF + k) * C1 + tx * 8 + 4)); \
                const float a0 = Arow[k];                                     \
                const float a1 = Arow[H + k];                                 \
                const float a2 = Arow[2 * H + k];                             \
                const float a3 = Arow[3 * H + k];                             \
                _Pragma("unroll")                                             \
                for (int r = 0; r < 4; r++) {                                 \
                    const float a = (r == 0) ? a0 : (r == 1) ? a1 : (r == 2) ? a2 : a3; \
                    acc[r][0] += a * w0.x; acc[r][1] += a * w0.y;             \
                    acc[r][2] += a * w0.z; acc[r][3] += a * w0.w;             \
                    acc[r][4] += a * w1.x; acc[r][5] += a * w1.y;             \
                    acc[r][6] += a * w1.z; acc[r][7] += a * w1.w;             \
                }                                                             \
            }                                                                 \
            _Pragma("unroll")                                                 \
            for (int r = 0; r < 4; r++) {                                     \
                const int n = base + ty * 4 + r;                              \
                if (n < N) {                                                  \
                    float v[8];                                               \
                    _Pragma("unroll")                                         \
                    for (int c = 0; c < 8; c++)                               \
                        v[c] = acc[r][c] + (ADDBIAS ? biasReg[c] : 0.0f);     \
                    float4* dst = (float4*)(DST + (size_t)n * C1 + tx * 8);   \
                    dst[0] = make_float4(v[0], v[1], v[2], v[3]);             \
                    dst[1] = make_float4(v[4], v[5], v[6], v[7]);             \
                }                                                             \
            }                                                                 \
        }
        PROJ_PASS(0,  g_Pt, 1)
        PROJ_PASS(64, g_Pb, 0)
        #undef PROJ_PASS
        __syncthreads();
    }
}

// ================= layer-1 stats (L2-bound gather pass) =================
__global__ __launch_bounds__(256)
void k_stats1(const void* __restrict__ ei, int E)
{
    const long long* ei64 = (const long long*)ei;
    const int*       ei32 = (const int*)ei;
    const int is64 = g_idx64;
    const int c = threadIdx.x;

    float s = 0.0f, q = 0.0f;
    for (int e = blockIdx.x; e < E; e += gridDim.x) {
        const long long col = is64 ? ei64[e]     : (long long)ei32[e];
        const long long row = is64 ? ei64[E + e] : (long long)ei32[E + e];
        const float v = g_Pt[col * C1 + c] + g_Pb[row * C1 + c];
        s += v;
        q += v * v;
    }
    atomicAdd(&g_s1[c], s);
    atomicAdd(&g_s1[C1 + c], q);
}

__global__ void k_fin1(float invE)
{
    const int c = threadIdx.x;
    if (c < C1) {
        const float m   = g_s1[c] * invE;
        const float var = g_s1[C1 + c] * invE - m * m;
        g_mr1[c]      = m;
        g_mr1[C1 + c] = rsqrtf(var + EPSV);
    }
}

// ================= layer 2: bf16-split warp MMA =================
// 256 threads = 8 warps; warp w computes rows [w*16, w*16+16) of a
// 128-row x 64-col tile, K = 256, via mma.sync.m16n8k16 bf16.
// Three passes: Ah@Bh + Ah@Bl + Al@Bh (drop al*bl ~ 2^-16).
#define ASTR 264               // A smem row stride (bf16 elems), 8-elem pad
#define BSTR 72                // B smem row stride (bf16 elems), 8-elem pad
#define A_BYTES (128 * ASTR * 2)
#define B_BYTES (C1 * BSTR * 2)

__global__ __launch_bounds__(256, 1)
void k_gemm2_mma(const void* __restrict__ ei,
                 const float* __restrict__ W2,
                 const float* __restrict__ b2,
                 int E)
{
    extern __shared__ char smraw[];
    __nv_bfloat16* Ah = (__nv_bfloat16*)smraw;
    __nv_bfloat16* Al = (__nv_bfloat16*)(smraw + A_BYTES);
    __nv_bfloat16* Bh = (__nv_bfloat16*)(smraw + 2 * A_BYTES);
    __nv_bfloat16* Bl = (__nv_bfloat16*)(smraw + 2 * A_BYTES + B_BYTES);
    float* Ms  = (float*)(smraw + 2 * A_BYTES + 2 * B_BYTES);
    float* Rs  = Ms + C1;
    float* b2s = Rs + C1;

    const int tid  = threadIdx.x;
    const int lane = tid & 31;
    const int wid  = tid >> 5;

    // --- build W2^T hi/lo: B[k][n] = W2[k][n] (k rows, n contiguous) ---
    for (int i = tid; i < C1 * C2; i += blockDim.x) {
        const int k = i >> 6, n = i & 63;
        const float w = W2[k * C2 + n];
        const __nv_bfloat16 hh = __float2bfloat16(w);
        const __nv_bfloat16 ll = __float2bfloat16(w - __bfloat162float(hh));
        Bh[k * BSTR + n] = hh;
        Bl[k * BSTR + n] = ll;
    }
    for (int i = tid; i < C1; i += blockDim.x) {
        Ms[i] = g_mr1[i];
        Rs[i] = g_mr1[C1 + i];
    }
    if (tid < C2) b2s[tid] = b2[tid];
    __syncthreads();

    const long long* ei64 = (const long long*)ei;
    const int*       ei32 = (const int*)ei;
    const int is64 = g_idx64;

    // lane-dependent ldmatrix base offsets (bytes)
    const uint32_t AhBase = smem_u32(Ah);
    const uint32_t AlBase = smem_u32(Al);
    const uint32_t BhBase = smem_u32(Bh);
    const uint32_t BlBase = smem_u32(Bl);
    const int M0 = wid * 16;
    // A: row = M0 + (lane&15), col = (lane>>4)*8
    const uint32_t aOff = (uint32_t)((M0 + (lane & 15)) * ASTR + (lane >> 4) * 8) * 2;
    // B: k = (lane&7) + ((lane>>3)&1)*8, n = (lane>>4)*8
    const uint32_t bOff = (uint32_t)(((lane & 7) + ((lane >> 3) & 1) * 8) * BSTR
                                     + (lane >> 4) * 8) * 2;

    // A-build indexing: 2 threads per row; thread covers 128 channels
    const int br   = tid & 127;       // row in tile
    const int bh_  = tid >> 7;        // channel half (0/1)
    const int qb   = bh_ * 32;        // starting float4 index (of 64)

    const int nTiles = (E + 127) / 128;
    for (int tile = blockIdx.x; tile < nTiles; tile += gridDim.x) {
        const int base = tile * 128;

        // ---- build A hi/lo tile ----
        {
            const int e = base + br;
            const bool valid = (e < E);
            long long ci = 0, ri = 0;
            if (valid) {
                ci = is64 ? ei64[e]     : (long long)ei32[e];
                ri = is64 ? ei64[E + e] : (long long)ei32[E + e];
            }
            const float4* pt = (const float4*)(g_Pt + ci * C1);
            const float4* pb = (const float4*)(g_Pb + ri * C1);
            uint32_t* ahRow = (uint32_t*)(Ah + br * ASTR);
            uint32_t* alRow = (uint32_t*)(Al + br * ASTR);
            #pragma unroll 8
            for (int j = 0; j < 32; j++) {
                const int q = qb + j;
                float4 a = make_float4(0.f, 0.f, 0.f, 0.f);
                float4 b = make_float4(0.f, 0.f, 0.f, 0.f);
                if (valid) { a = pt[q]; b = pb[q]; }
                const float4 ms = ((const float4*)Ms)[q];
                const float4 rs = ((const float4*)Rs)[q];
                float v0 = fmaxf(0.f, (a.x + b.x - ms.x) * rs.x);
                float v1 = fmaxf(0.f, (a.y + b.y - ms.y) * rs.y);
                float v2 = fmaxf(0.f, (a.z + b.z - ms.z) * rs.z);
                float v3 = fmaxf(0.f, (a.w + b.w - ms.w) * rs.w);
                if (!valid) { v0 = v1 = v2 = v3 = 0.f; }
                const __nv_bfloat162 h01 = __floats2bfloat162_rn(v0, v1);
                const __nv_bfloat162 h23 = __floats2bfloat162_rn(v2, v3);
                const float r0 = v0 - __bfloat162float(__low2bfloat16(h01));
                const float r1 = v1 - __bfloat162float(__high2bfloat16(h01));
                const float r2 = v2 - __bfloat162float(__low2bfloat16(h23));
                const float r3 = v3 - __bfloat162float(__high2bfloat16(h23));
                const __nv_bfloat162 l01 = __floats2bfloat162_rn(r0, r1);
                const __nv_bfloat162 l23 = __floats2bfloat162_rn(r2, r3);
                ahRow[q * 2 + 0] = *(const uint32_t*)&h01;
                ahRow[q * 2 + 1] = *(const uint32_t*)&h23;
                alRow[q * 2 + 0] = *(const uint32_t*)&l01;
                alRow[q * 2 + 1] = *(const uint32_t*)&l23;
            }
        }
        __syncthreads();

        // ---- MMA: 3 passes x 16 k-blocks x 8 n-blocks ----
        float acc[8][4];
        #pragma unroll
        for (int nb = 0; nb < 8; nb++)
            #pragma unroll
            for (int c = 0; c < 4; c++) acc[nb][c] = 0.0f;

        #pragma unroll
        for (int pass = 0; pass < 3; pass++) {
            const uint32_t aB = (pass == 2 ? AlBase : AhBase) + aOff;
            const uint32_t bB = (pass == 1 ? BlBase : BhBase) + bOff;
            #pragma unroll 4
            for (int kb = 0; kb < 16; kb++) {
                uint32_t a0, a1, a2, a3;
                ldsm_x4(a0, a1, a2, a3, aB + kb * 32);
                const uint32_t bk = bB + kb * (16 * BSTR * 2);
                #pragma unroll
                for (int nbp = 0; nbp < 4; nbp++) {
                    uint32_t b0, b1, b2_, b3_;
                    ldsm_x4_t(b0, b1, b2_, b3_, bk + nbp * 32);
                    mma16816(acc[nbp * 2 + 0], a0, a1, a2, a3, b0, b1);
                    mma16816(acc[nbp * 2 + 1], a0, a1, a2, a3, b2_, b3_);
                }
            }
        }

        // ---- epilogue: +bias, store Y2 ----
        {
            const int g  = lane >> 2;           // 0..7
            const int tg = lane & 3;            // 0..3
            const int e0 = base + M0 + g;
            const int e1 = e0 + 8;
            float* y0 = g_Y2 + (size_t)e0 * C2;
            float* y1 = g_Y2 + (size_t)e1 * C2;
            #pragma unroll
            for (int nb = 0; nb < 8; nb++) {
                const int c = nb * 8 + tg * 2;
                const float bx = b2s[c], by = b2s[c + 1];
                if (e0 < E) {
                    float2 o = make_float2(acc[nb][0] + bx, acc[nb][1] + by);
                    *(float2*)(y0 + c) = o;
                }
                if (e1 < E) {
                    float2 o = make_float2(acc[nb][2] + bx, acc[nb][3] + by);
                    *(float2*)(y1 + c) = o;
                }
            }
        }
        __syncthreads();
    }
}

// ================= layer-2 stats (dense, DRAM-bound) =================
__global__ __launch_bounds__(256)
void k_stats2(int E)
{
    __shared__ float rs[4][C2], rq[4][C2];
    const int c   = threadIdx.x & 63;
    const int sub = threadIdx.x >> 6;

    float s = 0.f, q = 0.f;
    for (int r = blockIdx.x * 4 + sub; r < E; r += gridDim.x * 4) {
        const float v = g_Y2[(size_t)r * C2 + c];
        s += v;
        q += v * v;
    }
    rs[sub][c] = s; rq[sub][c] = q;
    __syncthreads();
    if (threadIdx.x < C2) {
        float S = 0.f, Q = 0.f;
        #pragma unroll
        for (int g = 0; g < 4; g++) { S += rs[g][threadIdx.x]; Q += rq[g][threadIdx.x]; }
        atomicAdd(&g_s2[threadIdx.x], S);
        atomicAdd(&g_s2[C2 + threadIdx.x], Q);
    }
}

__global__ void k_fin2(float invE)
{
    const int c = threadIdx.x;
    if (c < C2) {
        const float m   = g_s2[c] * invE;
        const float var = g_s2[C2 + c] * invE - m * m;
        g_mr2[c]      = m;
        g_mr2[C2 + c] = rsqrtf(var + EPSV);
    }
}

// ================= layer 3 =================
__global__ void k_out(const float* __restrict__ W3,
                      const float* __restrict__ b3,
                      float* __restrict__ out,
                      int E)
{
    __shared__ float w[C2], m[C2], rs[C2];
    const int tid = threadIdx.x;
    if (tid < C2) {
        w[tid]  = W3[tid];
        m[tid]  = g_mr2[tid];
        rs[tid] = g_mr2[C2 + tid];
    }
    __syncthreads();

    const int lane = tid & 31;
    const int warp = tid >> 5;
    const int e = blockIdx.x * (blockDim.x >> 5) + warp;
    if (e >= E) return;

    const float2 y = ((const float2*)(g_Y2 + (size_t)e * C2))[lane];
    const int c = lane * 2;
    float p = fmaxf(0.f, (y.x - m[c])     * rs[c])     * w[c]
            + fmaxf(0.f, (y.y - m[c + 1]) * rs[c + 1]) * w[c + 1];
    #pragma unroll
    for (int o = 16; o > 0; o >>= 1) p += __shfl_down_sync(0xffffffffu, p, o);
    if (lane == 0) out[e] = p + b3[0];
}

// ================= launch =================
extern "C" void kernel_launch(void* const* d_in, const int* in_sizes, int n_in,
                              void* d_out, int out_size)
{
    const float* emb = (const float*)d_in[0];
    const void*  ei  = d_in[1];
    const float* W1  = (const float*)d_in[2];
    const float* b1  = (const float*)d_in[3];
    const float* W2  = (const float*)d_in[4];
    const float* b2  = (const float*)d_in[5];
    const float* W3  = (const float*)d_in[6];
    const float* b3  = (const float*)d_in[7];
    float* out = (float*)d_out;

    const int N = in_sizes[0] / H;
    const int E = in_sizes[1] / 2;

    int dev = 0;
    cudaGetDevice(&dev);
    int nsm = 148;
    cudaDeviceGetAttribute(&nsm, cudaDevAttrMultiProcessorCount, dev);

    const int smP = (K1DIM * C1 + 32 * H) * (int)sizeof(float);           // 139264
    const int smT = 2 * A_BYTES + 2 * B_BYTES + (2 * C1 + C2) * 4;        // ~211KB
    cudaFuncSetAttribute(k_proj,      cudaFuncAttributeMaxDynamicSharedMemorySize, smP);
    cudaFuncSetAttribute(k_gemm2_mma, cudaFuncAttributeMaxDynamicSharedMemorySize, smT);

    const int nTiles = (E + 127) / 128;
    const int g2 = nsm < nTiles ? nsm : nTiles;

    k_pre<<<2, 256>>>((const int*)ei);
    k_proj<<<nsm, 256, smP>>>(emb, W1, b1, N);
    k_stats1<<<nsm * 8, 256>>>(ei, E);
    k_fin1<<<1, 256>>>(1.0f / (float)E);
    k_gemm2_mma<<<g2, 256, smT>>>(ei, W2, b2, E);
    k_stats2<<<nsm * 8, 256>>>(E);
    k_fin2<<<1, 64>>>(1.0f / (float)E);
    k_out<<<(E + 7) / 8, 256>>>(W3, b3, out, E);
}

// round 6
// speedup vs baseline: 3.8390x; 1.4387x over previous
#include <cuda_runtime.h>
#include <cuda_bf16.h>
#include <cstdint>

#define NMAX 65536
#define EMAX 800000
#define K1DIM 128   // 2H
#define C1 256      // 4H
#define C2 64       // H
#define H  64
#define EPSV 1e-5f

// ---- warp MMA helpers (plain sm_103-compatible: no tcgen05) -------------
__device__ __forceinline__ uint32_t smem_u32(const void* p) {
    uint32_t a;
    asm("{ .reg .u64 t; cvta.to.shared.u64 t, %1; cvt.u32.u64 %0, t; }"
        : "=r"(a) : "l"(p));
    return a;
}
__device__ __forceinline__ void ldsm_x4(uint32_t& r0, uint32_t& r1,
                                        uint32_t& r2, uint32_t& r3, uint32_t addr) {
    asm volatile("ldmatrix.sync.aligned.m8n8.x4.shared.b16 {%0,%1,%2,%3}, [%4];"
                 : "=r"(r0), "=r"(r1), "=r"(r2), "=r"(r3) : "r"(addr));
}
__device__ __forceinline__ void ldsm_x4_t(uint32_t& r0, uint32_t& r1,
                                          uint32_t& r2, uint32_t& r3, uint32_t addr) {
    asm volatile("ldmatrix.sync.aligned.m8n8.x4.trans.shared.b16 {%0,%1,%2,%3}, [%4];"
                 : "=r"(r0), "=r"(r1), "=r"(r2), "=r"(r3) : "r"(addr));
}
__device__ __forceinline__ void mma16816(float* d,
                                         uint32_t a0, uint32_t a1, uint32_t a2, uint32_t a3,
                                         uint32_t b0, uint32_t b1) {
    asm volatile("mma.sync.aligned.m16n8k16.row.col.f32.bf16.bf16.f32 "
                 "{%0,%1,%2,%3}, {%4,%5,%6,%7}, {%8,%9}, {%0,%1,%2,%3};"
                 : "+f"(d[0]), "+f"(d[1]), "+f"(d[2]), "+f"(d[3])
                 : "r"(a0), "r"(a1), "r"(a2), "r"(a3), "r"(b0), "r"(b1));
}

// ================= scratch =================
__device__ float g_Pt[(size_t)NMAX * C1];
__device__ float g_Pb[(size_t)NMAX * C1];
__device__ float g_Y2[(size_t)EMAX * C2];
__device__ float g_s1[2 * C1];
__device__ float g_mr1[2 * C1];
__device__ float g_s2[2 * C2];
__device__ float g_mr2[2 * C2];
__device__ int   g_idx64;

// ================= pre =================
__global__ void k_pre(const int* __restrict__ ei_words)
{
    int gid = blockIdx.x * blockDim.x + threadIdx.x;
    if (gid == 0) {
        int orv = 0;
        #pragma unroll
        for (int i = 1; i < 32; i += 2) orv |= ei_words[i];
        g_idx64 = (orv == 0) ? 1 : 0;
    }
    if (gid < 2 * C1) g_s1[gid] = 0.0f;
    if (gid < 2 * C2) g_s2[gid] = 0.0f;
}

// ================= node projection (fp32 SIMT; small) =================
__global__ __launch_bounds__(256, 1)
void k_proj(const float* __restrict__ emb,
            const float* __restrict__ W1,
            const float* __restrict__ b1,
            int N)
{
    extern __shared__ float sm[];
    float* Ws = sm;                 // 128*256
    float* As = sm + K1DIM * C1;    // 32*64

    const int tid = threadIdx.x;
    for (int i = tid; i < K1DIM * C1 / 4; i += blockDim.x)
        ((float4*)Ws)[i] = ((const float4*)W1)[i];

    const int tx = tid & 31;
    const int ty = tid >> 5;

    float biasReg[8];
    #pragma unroll
    for (int c = 0; c < 8; c++) biasReg[c] = b1[tx * 8 + c];

    __syncthreads();

    const int nTiles = (N + 31) / 32;
    for (int tile = blockIdx.x; tile < nTiles; tile += gridDim.x) {
        const int base = tile * 32;
        for (int i = tid; i < 32 * 16; i += blockDim.x) {
            const int r = i >> 4, q = i & 15;
            const int n = base + r;
            float4 v = make_float4(0.f, 0.f, 0.f, 0.f);
            if (n < N) v = ((const float4*)(emb + (size_t)n * H))[q];
            ((float4*)(As + r * H))[q] = v;
        }
        __syncthreads();

        const float* Arow = As + (ty * 4) * H;

        #define PROJ_PASS(ROWOFF, DST, ADDBIAS)                               \
        {                                                                     \
            float acc[4][8];                                                  \
            _Pragma("unroll")                                                 \
            for (int r = 0; r < 4; r++)                                       \
                _Pragma("unroll")                                             \
                for (int c = 0; c < 8; c++) acc[r][c] = 0.0f;                 \
            _Pragma("unroll 4")                                               \
            for (int k = 0; k < H; k++) {                                     \
                const float4 w0 = *((const float4*)(Ws + (ROWOFF + k) * C1 + tx * 8));     \
                const float4 w1 = *((const float4*)(Ws + (ROWOFF + k) * C1 + tx * 8 + 4)); \
                const float a0 = Arow[k];                                     \
                const float a1 = Arow[H + k];                                 \
                const float a2 = Arow[2 * H + k];                             \
                const float a3 = Arow[3 * H + k];                             \
                _Pragma("unroll")                                             \
                for (int r = 0; r < 4; r++) {                                 \
                    const float a = (r == 0) ? a0 : (r == 1) ? a1 : (r == 2) ? a2 : a3; \
                    acc[r][0] += a * w0.x; acc[r][1] += a * w0.y;             \
                    acc[r][2] += a * w0.z; acc[r][3] += a * w0.w;             \
                    acc[r][4] += a * w1.x; acc[r][5] += a * w1.y;             \
                    acc[r][6] += a * w1.z; acc[r][7] += a * w1.w;             \
                }                                                             \
            }                                                                 \
            _Pragma("unroll")                                                 \
            for (int r = 0; r < 4; r++) {                                     \
                const int n = base + ty * 4 + r;                              \
                if (n < N) {                                                  \
                    float v[8];                                               \
                    _Pragma("unroll")                                         \
                    for (int c = 0; c < 8; c++)                               \
                        v[c] = acc[r][c] + (ADDBIAS ? biasReg[c] : 0.0f);     \
                    float4* dst = (float4*)(DST + (size_t)n * C1 + tx * 8);   \
                    dst[0] = make_float4(v[0], v[1], v[2], v[3]);             \
                    dst[1] = make_float4(v[4], v[5], v[6], v[7]);             \
                }                                                             \
            }                                                                 \
        }
        PROJ_PASS(0,  g_Pt, 1)
        PROJ_PASS(64, g_Pb, 0)
        #undef PROJ_PASS
        __syncthreads();
    }
}

// ================= layer-1 stats (L2 gather, 4-edge unroll for MLP) =====
__global__ __launch_bounds__(256)
void k_stats1(const void* __restrict__ ei, int E)
{
    const long long* ei64 = (const long long*)ei;
    const int*       ei32 = (const int*)ei;
    const int is64 = g_idx64;
    const int c = threadIdx.x;

    float s = 0.0f, q = 0.0f;
    const int stride = gridDim.x * 4;
    for (int e0 = blockIdx.x * 4; e0 < E; e0 += stride) {
        long long ci[4], ri[4];
        int nv = 0;
        #pragma unroll
        for (int j = 0; j < 4; j++) {
            const int e = e0 + j;
            if (e < E) {
                ci[j] = is64 ? ei64[e]     : (long long)ei32[e];
                ri[j] = is64 ? ei64[E + e] : (long long)ei32[E + e];
                nv = j + 1;
            }
        }
        float va[4], vb[4];
        #pragma unroll
        for (int j = 0; j < 4; j++) {
            if (j < nv) {
                va[j] = __ldg(g_Pt + ci[j] * C1 + c);
                vb[j] = __ldg(g_Pb + ri[j] * C1 + c);
            }
        }
        #pragma unroll
        for (int j = 0; j < 4; j++) {
            if (j < nv) {
                const float v = va[j] + vb[j];
                s += v;
                q += v * v;
            }
        }
    }
    atomicAdd(&g_s1[c], s);
    atomicAdd(&g_s1[C1 + c], q);
}

__global__ void k_fin1(float invE)
{
    const int c = threadIdx.x;
    if (c < C1) {
        const float m   = g_s1[c] * invE;
        const float var = g_s1[C1 + c] * invE - m * m;
        g_mr1[c]      = m;
        g_mr1[C1 + c] = rsqrtf(var + EPSV);
    }
}

// ================= layer 2: bf16-split warp MMA =================
// 512 threads = 16 warps. Tile = 128 edges x 64 cols, K = 256.
// Warp wm = wid&7 -> rows [wm*16, wm*16+16); wn = wid>>3 -> cols [wn*32, wn*32+32).
// Three passes: Ah@Bh + Ah@Bl + Al@Bh (drop al*bl ~ 2^-16).
#define ASTR 264               // A smem row stride (bf16 elems), 8-elem pad
#define BSTR 72                // B smem row stride (bf16 elems), 8-elem pad
#define A_BYTES (128 * ASTR * 2)
#define B_BYTES (C1 * BSTR * 2)

__global__ __launch_bounds__(512, 1)
void k_gemm2_mma(const void* __restrict__ ei,
                 const float* __restrict__ W2,
                 const float* __restrict__ b2,
                 int E)
{
    extern __shared__ char smraw[];
    __nv_bfloat16* Ah = (__nv_bfloat16*)smraw;
    __nv_bfloat16* Al = (__nv_bfloat16*)(smraw + A_BYTES);
    __nv_bfloat16* Bh = (__nv_bfloat16*)(smraw + 2 * A_BYTES);
    __nv_bfloat16* Bl = (__nv_bfloat16*)(smraw + 2 * A_BYTES + B_BYTES);
    float* Ms  = (float*)(smraw + 2 * A_BYTES + 2 * B_BYTES);
    float* Rs  = Ms + C1;
    float* b2s = Rs + C1;

    const int tid  = threadIdx.x;
    const int lane = tid & 31;
    const int wid  = tid >> 5;

    // --- build W2^T hi/lo: B[k][n] (k rows, n contiguous) ---
    for (int i = tid; i < C1 * C2; i += blockDim.x) {
        const int k = i >> 6, n = i & 63;
        const float w = W2[k * C2 + n];
        const __nv_bfloat16 hh = __float2bfloat16(w);
        const __nv_bfloat16 ll = __float2bfloat16(w - __bfloat162float(hh));
        Bh[k * BSTR + n] = hh;
        Bl[k * BSTR + n] = ll;
    }
    for (int i = tid; i < C1; i += blockDim.x) {
        Ms[i] = g_mr1[i];
        Rs[i] = g_mr1[C1 + i];
    }
    if (tid < C2) b2s[tid] = b2[tid];
    __syncthreads();

    const long long* ei64 = (const long long*)ei;
    const int*       ei32 = (const int*)ei;
    const int is64 = g_idx64;

    const uint32_t AhBase = smem_u32(Ah);
    const uint32_t AlBase = smem_u32(Al);
    const uint32_t BhBase = smem_u32(Bh);
    const uint32_t BlBase = smem_u32(Bl);

    const int wm = wid & 7;          // row group
    const int wn = wid >> 3;         // col half (0/1)
    const int M0 = wm * 16;
    // A frag: row = M0 + (lane&15), col chunk = (lane>>4)*8
    const uint32_t aOff = (uint32_t)((M0 + (lane & 15)) * ASTR + (lane >> 4) * 8) * 2;
    // B frag: k = (lane&7) + ((lane>>3)&1)*8, n = wn*32 + (lane>>4)*8
    const uint32_t bOff = (uint32_t)(((lane & 7) + ((lane >> 3) & 1) * 8) * BSTR
                                     + wn * 32 + (lane >> 4) * 8) * 2;

    const int nTiles = (E + 127) / 128;
    for (int tile = blockIdx.x; tile < nTiles; tile += gridDim.x) {
        const int base = tile * 128;

        // ---- build A hi/lo tile (coalesced: 64 threads per row) ----
        for (int i = tid; i < 128 * 64; i += 512) {
            const int r = i >> 6, q = i & 63;
            const int e = base + r;
            float4 a = make_float4(0.f, 0.f, 0.f, 0.f);
            float4 b = make_float4(0.f, 0.f, 0.f, 0.f);
            if (e < E) {
                const long long ci = is64 ? ei64[e]     : (long long)ei32[e];
                const long long ri = is64 ? ei64[E + e] : (long long)ei32[E + e];
                a = ((const float4*)(g_Pt + ci * C1))[q];
                b = ((const float4*)(g_Pb + ri * C1))[q];
            }
            const float4 ms = ((const float4*)Ms)[q];
            const float4 rs = ((const float4*)Rs)[q];
            float v0 = fmaxf(0.f, (a.x + b.x - ms.x) * rs.x);
            float v1 = fmaxf(0.f, (a.y + b.y - ms.y) * rs.y);
            float v2 = fmaxf(0.f, (a.z + b.z - ms.z) * rs.z);
            float v3 = fmaxf(0.f, (a.w + b.w - ms.w) * rs.w);
            if (base + r >= E) { v0 = v1 = v2 = v3 = 0.f; }
            const __nv_bfloat162 h01 = __floats2bfloat162_rn(v0, v1);
            const __nv_bfloat162 h23 = __floats2bfloat162_rn(v2, v3);
            const float r0 = v0 - __bfloat162float(__low2bfloat16(h01));
            const float r1 = v1 - __bfloat162float(__high2bfloat16(h01));
            const float r2 = v2 - __bfloat162float(__low2bfloat16(h23));
            const float r3 = v3 - __bfloat162float(__high2bfloat16(h23));
            const __nv_bfloat162 l01 = __floats2bfloat162_rn(r0, r1);
            const __nv_bfloat162 l23 = __floats2bfloat162_rn(r2, r3);
            uint32_t* ahRow = (uint32_t*)(Ah + r * ASTR);
            uint32_t* alRow = (uint32_t*)(Al + r * ASTR);
            ahRow[q * 2 + 0] = *(const uint32_t*)&h01;
            ahRow[q * 2 + 1] = *(const uint32_t*)&h23;
            alRow[q * 2 + 0] = *(const uint32_t*)&l01;
            alRow[q * 2 + 1] = *(const uint32_t*)&l23;
        }
        __syncthreads();

        // ---- MMA: 3 passes x 16 k-blocks x (2 ldsm_t + 4 mma) ----
        float acc[4][4];
        #pragma unroll
        for (int nb = 0; nb < 4; nb++)
            #pragma unroll
            for (int c = 0; c < 4; c++) acc[nb][c] = 0.0f;

        #pragma unroll
        for (int pass = 0; pass < 3; pass++) {
            const uint32_t aB = (pass == 2 ? AlBase : AhBase) + aOff;
            const uint32_t bB = (pass == 1 ? BlBase : BhBase) + bOff;
            #pragma unroll 4
            for (int kb = 0; kb < 16; kb++) {
                uint32_t a0, a1, a2, a3;
                ldsm_x4(a0, a1, a2, a3, aB + kb * 32);
                const uint32_t bk = bB + kb * (16 * BSTR * 2);
                #pragma unroll
                for (int nbp = 0; nbp < 2; nbp++) {
                    uint32_t b0, b1, b2_, b3_;
                    ldsm_x4_t(b0, b1, b2_, b3_, bk + nbp * 32);
                    mma16816(acc[nbp * 2 + 0], a0, a1, a2, a3, b0, b1);
                    mma16816(acc[nbp * 2 + 1], a0, a1, a2, a3, b2_, b3_);
                }
            }
        }

        // ---- epilogue: +bias, store Y2 ----
        {
            const int g  = lane >> 2;           // 0..7
            const int tg = lane & 3;            // 0..3
            const int e0 = base + M0 + g;
            const int e1 = e0 + 8;
            float* y0 = g_Y2 + (size_t)e0 * C2;
            float* y1 = g_Y2 + (size_t)e1 * C2;
            #pragma unroll
            for (int nb = 0; nb < 4; nb++) {
                const int c = wn * 32 + nb * 8 + tg * 2;
                const float bx = b2s[c], by = b2s[c + 1];
                if (e0 < E) {
                    float2 o = make_float2(acc[nb][0] + bx, acc[nb][1] + by);
                    *(float2*)(y0 + c) = o;
                }
                if (e1 < E) {
                    float2 o = make_float2(acc[nb][2] + bx, acc[nb][3] + by);
                    *(float2*)(y1 + c) = o;
                }
            }
        }
        __syncthreads();
    }
}

// ================= layer-2 stats (dense, DRAM-bound) =================
__global__ __launch_bounds__(256)
void k_stats2(int E)
{
    __shared__ float rs[4][C2], rq[4][C2];
    const int c   = threadIdx.x & 63;
    const int sub = threadIdx.x >> 6;

    float s = 0.f, q = 0.f;
    for (int r = blockIdx.x * 4 + sub; r < E; r += gridDim.x * 4) {
        const float v = g_Y2[(size_t)r * C2 + c];
        s += v;
        q += v * v;
    }
    rs[sub][c] = s; rq[sub][c] = q;
    __syncthreads();
    if (threadIdx.x < C2) {
        float S = 0.f, Q = 0.f;
        #pragma unroll
        for (int g = 0; g < 4; g++) { S += rs[g][threadIdx.x]; Q += rq[g][threadIdx.x]; }
        atomicAdd(&g_s2[threadIdx.x], S);
        atomicAdd(&g_s2[C2 + threadIdx.x], Q);
    }
}

__global__ void k_fin2(float invE)
{
    const int c = threadIdx.x;
    if (c < C2) {
        const float m   = g_s2[c] * invE;
        const float var = g_s2[C2 + c] * invE - m * m;
        g_mr2[c]      = m;
        g_mr2[C2 + c] = rsqrtf(var + EPSV);
    }
}

// ================= layer 3 =================
__global__ void k_out(const float* __restrict__ W3,
                      const float* __restrict__ b3,
                      float* __restrict__ out,
                      int E)
{
    __shared__ float w[C2], m[C2], rs[C2];
    const int tid = threadIdx.x;
    if (tid < C2) {
        w[tid]  = W3[tid];
        m[tid]  = g_mr2[tid];
        rs[tid] = g_mr2[C2 + tid];
    }
    __syncthreads();

    const int lane = tid & 31;
    const int warp = tid >> 5;
    const int e = blockIdx.x * (blockDim.x >> 5) + warp;
    if (e >= E) return;

    const float2 y = ((const float2*)(g_Y2 + (size_t)e * C2))[lane];
    const int c = lane * 2;
    float p = fmaxf(0.f, (y.x - m[c])     * rs[c])     * w[c]
            + fmaxf(0.f, (y.y - m[c + 1]) * rs[c + 1]) * w[c + 1];
    #pragma unroll
    for (int o = 16; o > 0; o >>= 1) p += __shfl_down_sync(0xffffffffu, p, o);
    if (lane == 0) out[e] = p + b3[0];
}

// ================= launch =================
extern "C" void kernel_launch(void* const* d_in, const int* in_sizes, int n_in,
                              void* d_out, int out_size)
{
    const float* emb = (const float*)d_in[0];
    const void*  ei  = d_in[1];
    const float* W1  = (const float*)d_in[2];
    const float* b1  = (const float*)d_in[3];
    const float* W2  = (const float*)d_in[4];
    const float* b2  = (const float*)d_in[5];
    const float* W3  = (const float*)d_in[6];
    const float* b3  = (const float*)d_in[7];
    float* out = (float*)d_out;

    const int N = in_sizes[0] / H;
    const int E = in_sizes[1] / 2;

    int dev = 0;
    cudaGetDevice(&dev);
    int nsm = 148;
    cudaDeviceGetAttribute(&nsm, cudaDevAttrMultiProcessorCount, dev);

    const int smP = (K1DIM * C1 + 32 * H) * (int)sizeof(float);           // 139264
    const int smT = 2 * A_BYTES + 2 * B_BYTES + (2 * C1 + C2) * 4;        // ~211KB
    cudaFuncSetAttribute(k_proj,      cudaFuncAttributeMaxDynamicSharedMemorySize, smP);
    cudaFuncSetAttribute(k_gemm2_mma, cudaFuncAttributeMaxDynamicSharedMemorySize, smT);

    const int nTiles = (E + 127) / 128;
    const int g2 = nsm < nTiles ? nsm : nTiles;

    k_pre<<<2, 256>>>((const int*)ei);
    k_proj<<<nsm, 256, smP>>>(emb, W1, b1, N);
    k_stats1<<<nsm * 8, 256>>>(ei, E);
    k_fin1<<<1, 256>>>(1.0f / (float)E);
    k_gemm2_mma<<<g2, 512, smT>>>(ei, W2, b2, E);
    k_stats2<<<nsm * 8, 256>>>(E);
    k_fin2<<<1, 64>>>(1.0f / (float)E);
    k_out<<<(E + 7) / 8, 256>>>(W3, b3, out, E);
}

// round 7
// speedup vs baseline: 4.4452x; 1.1579x over previous
#include <cuda_runtime.h>
#include <cuda_bf16.h>
#include <cstdint>

#define NMAX 65536
#define EMAX 800000
#define K1DIM 128   // 2H
#define C1 256      // 4H
#define C2 64       // H
#define H  64
#define EPSV 1e-5f

// ---- warp MMA helpers (plain sm_103-compatible: no tcgen05) -------------
__device__ __forceinline__ uint32_t smem_u32(const void* p) {
    uint32_t a;
    asm("{ .reg .u64 t; cvta.to.shared.u64 t, %1; cvt.u32.u64 %0, t; }"
        : "=r"(a) : "l"(p));
    return a;
}
__device__ __forceinline__ void ldsm_x4(uint32_t& r0, uint32_t& r1,
                                        uint32_t& r2, uint32_t& r3, uint32_t addr) {
    asm volatile("ldmatrix.sync.aligned.m8n8.x4.shared.b16 {%0,%1,%2,%3}, [%4];"
                 : "=r"(r0), "=r"(r1), "=r"(r2), "=r"(r3) : "r"(addr));
}
__device__ __forceinline__ void ldsm_x4_t(uint32_t& r0, uint32_t& r1,
                                          uint32_t& r2, uint32_t& r3, uint32_t addr) {
    asm volatile("ldmatrix.sync.aligned.m8n8.x4.trans.shared.b16 {%0,%1,%2,%3}, [%4];"
                 : "=r"(r0), "=r"(r1), "=r"(r2), "=r"(r3) : "r"(addr));
}
__device__ __forceinline__ void mma16816(float* d,
                                         uint32_t a0, uint32_t a1, uint32_t a2, uint32_t a3,
                                         uint32_t b0, uint32_t b1) {
    asm volatile("mma.sync.aligned.m16n8k16.row.col.f32.bf16.bf16.f32 "
                 "{%0,%1,%2,%3}, {%4,%5,%6,%7}, {%8,%9}, {%0,%1,%2,%3};"
                 : "+f"(d[0]), "+f"(d[1]), "+f"(d[2]), "+f"(d[3])
                 : "r"(a0), "r"(a1), "r"(a2), "r"(a3), "r"(b0), "r"(b1));
}

// ================= scratch =================
__device__ float    g_Pt[(size_t)NMAX * C1];     // fp32 planes (gemm2)
__device__ float    g_Pb[(size_t)NMAX * C1];
__device__ uint32_t g_PtH[(size_t)NMAX * 128];   // bf16x2 planes (stats1)
__device__ uint32_t g_PbH[(size_t)NMAX * 128];
__device__ float    g_Y2[(size_t)EMAX * C2];
__device__ float    g_s1[2 * C1];
__device__ float    g_mr1[2 * C1];
__device__ float    g_s2[2 * C2];
__device__ float    g_mr2[2 * C2];
__device__ int      g_idx64;

// ================= pre =================
__global__ void k_pre(const int* __restrict__ ei_words)
{
    int gid = blockIdx.x * blockDim.x + threadIdx.x;
    if (gid == 0) {
        int orv = 0;
        #pragma unroll
        for (int i = 1; i < 32; i += 2) orv |= ei_words[i];
        g_idx64 = (orv == 0) ? 1 : 0;
    }
    if (gid < 2 * C1) g_s1[gid] = 0.0f;
    if (gid < 2 * C2) g_s2[gid] = 0.0f;
}

// ================= node projection (fp32 SIMT) =================
__global__ __launch_bounds__(256, 1)
void k_proj(const float* __restrict__ emb,
            const float* __restrict__ W1,
            const float* __restrict__ b1,
            int N)
{
    extern __shared__ float sm[];
    float* Ws = sm;                 // 128*256
    float* As = sm + K1DIM * C1;    // 32*64

    const int tid = threadIdx.x;
    for (int i = tid; i < K1DIM * C1 / 4; i += blockDim.x)
        ((float4*)Ws)[i] = ((const float4*)W1)[i];

    const int tx = tid & 31;
    const int ty = tid >> 5;

    float biasReg[8];
    #pragma unroll
    for (int c = 0; c < 8; c++) biasReg[c] = b1[tx * 8 + c];

    __syncthreads();

    const int nTiles = (N + 31) / 32;
    for (int tile = blockIdx.x; tile < nTiles; tile += gridDim.x) {
        const int base = tile * 32;
        for (int i = tid; i < 32 * 16; i += blockDim.x) {
            const int r = i >> 4, q = i & 15;
            const int n = base + r;
            float4 v = make_float4(0.f, 0.f, 0.f, 0.f);
            if (n < N) v = ((const float4*)(emb + (size_t)n * H))[q];
            ((float4*)(As + r * H))[q] = v;
        }
        __syncthreads();

        const float* Arow = As + (ty * 4) * H;

        #define PROJ_PASS(ROWOFF, DST, DSTH, ADDBIAS)                         \
        {                                                                     \
            float acc[4][8];                                                  \
            _Pragma("unroll")                                                 \
            for (int r = 0; r < 4; r++)                                       \
                _Pragma("unroll")                                             \
                for (int c = 0; c < 8; c++) acc[r][c] = 0.0f;                 \
            _Pragma("unroll 4")                                               \
            for (int k = 0; k < H; k++) {                                     \
                const float4 w0 = *((const float4*)(Ws + (ROWOFF + k) * C1 + tx * 8));     \
                const float4 w1 = *((const float4*)(Ws + (ROWOFF + k) * C1 + tx * 8 + 4)); \
                const float a0 = Arow[k];                                     \
                const float a1 = Arow[H + k];                                 \
                const float a2 = Arow[2 * H + k];                             \
                const float a3 = Arow[3 * H + k];                             \
                _Pragma("unroll")                                             \
                for (int r = 0; r < 4; r++) {                                 \
                    const float a = (r == 0) ? a0 : (r == 1) ? a1 : (r == 2) ? a2 : a3; \
                    acc[r][0] += a * w0.x; acc[r][1] += a * w0.y;             \
                    acc[r][2] += a * w0.z; acc[r][3] += a * w0.w;             \
                    acc[r][4] += a * w1.x; acc[r][5] += a * w1.y;             \
                    acc[r][6] += a * w1.z; acc[r][7] += a * w1.w;             \
                }                                                             \
            }                                                                 \
            _Pragma("unroll")                                                 \
            for (int r = 0; r < 4; r++) {                                     \
                const int n = base + ty * 4 + r;                              \
                if (n < N) {                                                  \
                    float v[8];                                               \
                    _Pragma("unroll")                                         \
                    for (int c = 0; c < 8; c++)                               \
                        v[c] = acc[r][c] + (ADDBIAS ? biasReg[c] : 0.0f);     \
                    float4* dst = (float4*)(DST + (size_t)n * C1 + tx * 8);   \
                    dst[0] = make_float4(v[0], v[1], v[2], v[3]);             \
                    dst[1] = make_float4(v[4], v[5], v[6], v[7]);             \
                    const __nv_bfloat162 p01 = __floats2bfloat162_rn(v[0], v[1]); \
                    const __nv_bfloat162 p23 = __floats2bfloat162_rn(v[2], v[3]); \
                    const __nv_bfloat162 p45 = __floats2bfloat162_rn(v[4], v[5]); \
                    const __nv_bfloat162 p67 = __floats2bfloat162_rn(v[6], v[7]); \
                    uint4 u;                                                  \
                    u.x = *(const uint32_t*)&p01; u.y = *(const uint32_t*)&p23; \
                    u.z = *(const uint32_t*)&p45; u.w = *(const uint32_t*)&p67; \
                    ((uint4*)(DSTH + (size_t)n * 128))[tx] = u;               \
                }                                                             \
            }                                                                 \
        }
        PROJ_PASS(0,  g_Pt, g_PtH, 1)
        PROJ_PASS(64, g_Pb, g_PbH, 0)
        #undef PROJ_PASS
        __syncthreads();
    }
}

// ================= layer-1 stats (bf16 planes, half traffic) =============
// 256 threads: thread = (half, c2); c2 covers channels {2c2, 2c2+1};
// half picks 4-edge group. 4-edge unroll -> 8 row loads in flight.
__global__ __launch_bounds__(256)
void k_stats1(const void* __restrict__ ei, int E)
{
    const long long* ei64 = (const long long*)ei;
    const int*       ei32 = (const int*)ei;
    const int is64 = g_idx64;
    const int c2   = threadIdx.x & 127;
    const int half = threadIdx.x >> 7;

    float s0 = 0.f, q0 = 0.f, s1 = 0.f, q1 = 0.f;
    const int stride = gridDim.x * 8;
    for (int e0 = blockIdx.x * 8 + half * 4; e0 < E; e0 += stride) {
        uint32_t ta[4], tb[4];
        int nv = 0;
        #pragma unroll
        for (int j = 0; j < 4; j++) {
            const int e = e0 + j;
            if (e < E) {
                const long long ci = is64 ? ei64[e]     : (long long)ei32[e];
                const long long ri = is64 ? ei64[E + e] : (long long)ei32[E + e];
                ta[j] = __ldg(g_PtH + ci * 128 + c2);
                tb[j] = __ldg(g_PbH + ri * 128 + c2);
                nv = j + 1;
            }
        }
        #pragma unroll
        for (int j = 0; j < 4; j++) {
            if (j < nv) {
                const float2 af = __bfloat1622float2(*(const __nv_bfloat162*)&ta[j]);
                const float2 bf = __bfloat1622float2(*(const __nv_bfloat162*)&tb[j]);
                const float v0 = af.x + bf.x;
                const float v1 = af.y + bf.y;
                s0 += v0; q0 += v0 * v0;
                s1 += v1; q1 += v1 * v1;
            }
        }
    }
    atomicAdd(&g_s1[2 * c2],          s0);
    atomicAdd(&g_s1[2 * c2 + 1],      s1);
    atomicAdd(&g_s1[C1 + 2 * c2],     q0);
    atomicAdd(&g_s1[C1 + 2 * c2 + 1], q1);
}

__global__ void k_fin1(float invE)
{
    const int c = threadIdx.x;
    if (c < C1) {
        const float m   = g_s1[c] * invE;
        const float var = g_s1[C1 + c] * invE - m * m;
        g_mr1[c]      = m;
        g_mr1[C1 + c] = rsqrtf(var + EPSV);
    }
}

// ================= layer 2: bf16-split warp MMA + fused stats2 ===========
// 512 threads = 16 warps. Tile = 128 edges x 64 cols, K = 256.
// Warp wm = wid&7 -> rows [wm*16, wm*16+16); wn = wid>>3 -> cols [wn*32,+32).
// Three passes: Ah@Bh + Ah@Bl + Al@Bh (drop al*bl ~ 2^-16).
#define ASTR 264               // A smem row stride (bf16 elems), 8-elem pad
#define BSTR 72                // B smem row stride (bf16 elems), 8-elem pad
#define A_BYTES (128 * ASTR * 2)
#define B_BYTES (C1 * BSTR * 2)

__global__ __launch_bounds__(512, 1)
void k_gemm2_mma(const void* __restrict__ ei,
                 const float* __restrict__ W2,
                 const float* __restrict__ b2,
                 int E)
{
    extern __shared__ char smraw[];
    __nv_bfloat16* Ah = (__nv_bfloat16*)smraw;
    __nv_bfloat16* Al = (__nv_bfloat16*)(smraw + A_BYTES);
    __nv_bfloat16* Bh = (__nv_bfloat16*)(smraw + 2 * A_BYTES);
    __nv_bfloat16* Bl = (__nv_bfloat16*)(smraw + 2 * A_BYTES + B_BYTES);
    float* Ms  = (float*)(smraw + 2 * A_BYTES + 2 * B_BYTES);
    float* Rs  = Ms + C1;
    float* b2s = Rs + C1;

    const int tid  = threadIdx.x;
    const int lane = tid & 31;
    const int wid  = tid >> 5;

    // --- build W2^T hi/lo: B[k][n] (k rows, n contiguous) ---
    for (int i = tid; i < C1 * C2; i += blockDim.x) {
        const int k = i >> 6, n = i & 63;
        const float w = W2[k * C2 + n];
        const __nv_bfloat16 hh = __float2bfloat16(w);
        const __nv_bfloat16 ll = __float2bfloat16(w - __bfloat162float(hh));
        Bh[k * BSTR + n] = hh;
        Bl[k * BSTR + n] = ll;
    }
    for (int i = tid; i < C1; i += blockDim.x) {
        Ms[i] = g_mr1[i];
        Rs[i] = g_mr1[C1 + i];
    }
    if (tid < C2) b2s[tid] = b2[tid];
    __syncthreads();

    const long long* ei64 = (const long long*)ei;
    const int*       ei32 = (const int*)ei;
    const int is64 = g_idx64;

    const uint32_t AhBase = smem_u32(Ah);
    const uint32_t AlBase = smem_u32(Al);
    const uint32_t BhBase = smem_u32(Bh);
    const uint32_t BlBase = smem_u32(Bl);

    const int wm = wid & 7;          // row group
    const int wn = wid >> 3;         // col half (0/1)
    const int M0 = wm * 16;
    const uint32_t aOff = (uint32_t)((M0 + (lane & 15)) * ASTR + (lane >> 4) * 8) * 2;
    const uint32_t bOff = (uint32_t)(((lane & 7) + ((lane >> 3) & 1) * 8) * BSTR
                                     + wn * 32 + (lane >> 4) * 8) * 2;

    // fused stats2 accumulators: 8 owned columns (wn*32 + nb*8 + tg*2 + {0,1})
    float sSum[8], sSq[8];
    #pragma unroll
    for (int i = 0; i < 8; i++) { sSum[i] = 0.f; sSq[i] = 0.f; }

    const int nTiles = (E + 127) / 128;
    for (int tile = blockIdx.x; tile < nTiles; tile += gridDim.x) {
        const int base = tile * 128;

        // ---- build A hi/lo tile (coalesced: 64 threads per row) ----
        for (int i = tid; i < 128 * 64; i += 512) {
            const int r = i >> 6, q = i & 63;
            const int e = base + r;
            float4 a = make_float4(0.f, 0.f, 0.f, 0.f);
            float4 b = make_float4(0.f, 0.f, 0.f, 0.f);
            if (e < E) {
                const long long ci = is64 ? ei64[e]     : (long long)ei32[e];
                const long long ri = is64 ? ei64[E + e] : (long long)ei32[E + e];
                a = ((const float4*)(g_Pt + ci * C1))[q];
                b = ((const float4*)(g_Pb + ri * C1))[q];
            }
            const float4 ms = ((const float4*)Ms)[q];
            const float4 rs = ((const float4*)Rs)[q];
            float v0 = fmaxf(0.f, (a.x + b.x - ms.x) * rs.x);
            float v1 = fmaxf(0.f, (a.y + b.y - ms.y) * rs.y);
            float v2 = fmaxf(0.f, (a.z + b.z - ms.z) * rs.z);
            float v3 = fmaxf(0.f, (a.w + b.w - ms.w) * rs.w);
            if (e >= E) { v0 = v1 = v2 = v3 = 0.f; }
            const __nv_bfloat162 h01 = __floats2bfloat162_rn(v0, v1);
            const __nv_bfloat162 h23 = __floats2bfloat162_rn(v2, v3);
            const float r0 = v0 - __bfloat162float(__low2bfloat16(h01));
            const float r1 = v1 - __bfloat162float(__high2bfloat16(h01));
            const float r2 = v2 - __bfloat162float(__low2bfloat16(h23));
            const float r3 = v3 - __bfloat162float(__high2bfloat16(h23));
            const __nv_bfloat162 l01 = __floats2bfloat162_rn(r0, r1);
            const __nv_bfloat162 l23 = __floats2bfloat162_rn(r2, r3);
            uint32_t* ahRow = (uint32_t*)(Ah + r * ASTR);
            uint32_t* alRow = (uint32_t*)(Al + r * ASTR);
            ahRow[q * 2 + 0] = *(const uint32_t*)&h01;
            ahRow[q * 2 + 1] = *(const uint32_t*)&h23;
            alRow[q * 2 + 0] = *(const uint32_t*)&l01;
            alRow[q * 2 + 1] = *(const uint32_t*)&l23;
        }
        __syncthreads();

        // ---- MMA: 3 passes x 16 k-blocks x (2 ldsm_t + 4 mma) ----
        float acc[4][4];
        #pragma unroll
        for (int nb = 0; nb < 4; nb++)
            #pragma unroll
            for (int c = 0; c < 4; c++) acc[nb][c] = 0.0f;

        #pragma unroll
        for (int pass = 0; pass < 3; pass++) {
            const uint32_t aB = (pass == 2 ? AlBase : AhBase) + aOff;
            const uint32_t bB = (pass == 1 ? BlBase : BhBase) + bOff;
            #pragma unroll 4
            for (int kb = 0; kb < 16; kb++) {
                uint32_t a0, a1, a2, a3;
                ldsm_x4(a0, a1, a2, a3, aB + kb * 32);
                const uint32_t bk = bB + kb * (16 * BSTR * 2);
                #pragma unroll
                for (int nbp = 0; nbp < 2; nbp++) {
                    uint32_t b0, b1, b2_, b3_;
                    ldsm_x4_t(b0, b1, b2_, b3_, bk + nbp * 32);
                    mma16816(acc[nbp * 2 + 0], a0, a1, a2, a3, b0, b1);
                    mma16816(acc[nbp * 2 + 1], a0, a1, a2, a3, b2_, b3_);
                }
            }
        }

        // ---- epilogue: +bias, store Y2, accumulate stats2 ----
        {
            const int g  = lane >> 2;           // 0..7
            const int tg = lane & 3;            // 0..3
            const int e0 = base + M0 + g;
            const int e1 = e0 + 8;
            float* y0 = g_Y2 + (size_t)e0 * C2;
            float* y1 = g_Y2 + (size_t)e1 * C2;
            #pragma unroll
            for (int nb = 0; nb < 4; nb++) {
                const int c = wn * 32 + nb * 8 + tg * 2;
                const float bx = b2s[c], by = b2s[c + 1];
                if (e0 < E) {
                    const float ox = acc[nb][0] + bx;
                    const float oy = acc[nb][1] + by;
                    *(float2*)(y0 + c) = make_float2(ox, oy);
                    sSum[nb * 2 + 0] += ox; sSq[nb * 2 + 0] += ox * ox;
                    sSum[nb * 2 + 1] += oy; sSq[nb * 2 + 1] += oy * oy;
                }
                if (e1 < E) {
                    const float ox = acc[nb][2] + bx;
                    const float oy = acc[nb][3] + by;
                    *(float2*)(y1 + c) = make_float2(ox, oy);
                    sSum[nb * 2 + 0] += ox; sSq[nb * 2 + 0] += ox * ox;
                    sSum[nb * 2 + 1] += oy; sSq[nb * 2 + 1] += oy * oy;
                }
            }
        }
        __syncthreads();
    }

    // ---- stats2 reduction: smem (reuse Ms region), then global atomics ----
    float* sS = Ms;          // 64 floats
    float* sQ = Ms + 64;     // 64 floats
    __syncthreads();
    if (tid < 128) Ms[tid] = 0.f;
    __syncthreads();
    {
        const int tg = lane & 3;
        #pragma unroll
        for (int nb = 0; nb < 4; nb++) {
            const int c = wn * 32 + nb * 8 + tg * 2;
            atomicAdd(&sS[c],     sSum[nb * 2 + 0]);
            atomicAdd(&sS[c + 1], sSum[nb * 2 + 1]);
            atomicAdd(&sQ[c],     sSq[nb * 2 + 0]);
            atomicAdd(&sQ[c + 1], sSq[nb * 2 + 1]);
        }
    }
    __syncthreads();
    if (tid < C2) {
        atomicAdd(&g_s2[tid],      sS[tid]);
        atomicAdd(&g_s2[C2 + tid], sQ[tid]);
    }
}

__global__ void k_fin2(float invE)
{
    const int c = threadIdx.x;
    if (c < C2) {
        const float m   = g_s2[c] * invE;
        const float var = g_s2[C2 + c] * invE - m * m;
        g_mr2[c]      = m;
        g_mr2[C2 + c] = rsqrtf(var + EPSV);
    }
}

// ================= layer 3 =================
__global__ void k_out(const float* __restrict__ W3,
                      const float* __restrict__ b3,
                      float* __restrict__ out,
                      int E)
{
    __shared__ float w[C2], m[C2], rs[C2];
    const int tid = threadIdx.x;
    if (tid < C2) {
        w[tid]  = W3[tid];
        m[tid]  = g_mr2[tid];
        rs[tid] = g_mr2[C2 + tid];
    }
    __syncthreads();

    const int lane = tid & 31;
    const int warp = tid >> 5;
    const int e = blockIdx.x * (blockDim.x >> 5) + warp;
    if (e >= E) return;

    const float2 y = ((const float2*)(g_Y2 + (size_t)e * C2))[lane];
    const int c = lane * 2;
    float p = fmaxf(0.f, (y.x - m[c])     * rs[c])     * w[c]
            + fmaxf(0.f, (y.y - m[c + 1]) * rs[c + 1]) * w[c + 1];
    #pragma unroll
    for (int o = 16; o > 0; o >>= 1) p += __shfl_down_sync(0xffffffffu, p, o);
    if (lane == 0) out[e] = p + b3[0];
}

// ================= launch =================
extern "C" void kernel_launch(void* const* d_in, const int* in_sizes, int n_in,
                              void* d_out, int out_size)
{
    const float* emb = (const float*)d_in[0];
    const void*  ei  = d_in[1];
    const float* W1  = (const float*)d_in[2];
    const float* b1  = (const float*)d_in[3];
    const float* W2  = (const float*)d_in[4];
    const float* b2  = (const float*)d_in[5];
    const float* W3  = (const float*)d_in[6];
    const float* b3  = (const float*)d_in[7];
    float* out = (float*)d_out;

    const int N = in_sizes[0] / H;
    const int E = in_sizes[1] / 2;

    int dev = 0;
    cudaGetDevice(&dev);
    int nsm = 148;
    cudaDeviceGetAttribute(&nsm, cudaDevAttrMultiProcessorCount, dev);

    const int smP = (K1DIM * C1 + 32 * H) * (int)sizeof(float);           // 139264
    const int smT = 2 * A_BYTES + 2 * B_BYTES + (2 * C1 + C2) * 4;        // ~211KB
    cudaFuncSetAttribute(k_proj,      cudaFuncAttributeMaxDynamicSharedMemorySize, smP);
    cudaFuncSetAttribute(k_gemm2_mma, cudaFuncAttributeMaxDynamicSharedMemorySize, smT);

    const int nTiles = (E + 127) / 128;
    const int g2 = nsm < nTiles ? nsm : nTiles;

    k_pre<<<2, 256>>>((const int*)ei);
    k_proj<<<nsm, 256, smP>>>(emb, W1, b1, N);
    k_stats1<<<nsm * 8, 256>>>(ei, E);
    k_fin1<<<1, 256>>>(1.0f / (float)E);
    k_gemm2_mma<<<g2, 512, smT>>>(ei, W2, b2, E);
    k_fin2<<<1, 64>>>(1.0f / (float)E);
    k_out<<<(E + 7) / 8, 256>>>(W3, b3, out, E);
}

// round 8
// speedup vs baseline: 4.8046x; 1.0809x over previous
#include <cuda_runtime.h>
#include <cuda_bf16.h>
#include <cstdint>

#define NMAX 65536
#define EMAX 800000
#define K1DIM 128   // 2H
#define C1 256      // 4H
#define C2 64       // H
#define H  64
#define EPSV 1e-5f

// ---- warp MMA helpers (plain sm_103-compatible: no tcgen05) -------------
__device__ __forceinline__ uint32_t smem_u32(const void* p) {
    uint32_t a;
    asm("{ .reg .u64 t; cvta.to.shared.u64 t, %1; cvt.u32.u64 %0, t; }"
        : "=r"(a) : "l"(p));
    return a;
}
__device__ __forceinline__ void ldsm_x4(uint32_t& r0, uint32_t& r1,
                                        uint32_t& r2, uint32_t& r3, uint32_t addr) {
    asm volatile("ldmatrix.sync.aligned.m8n8.x4.shared.b16 {%0,%1,%2,%3}, [%4];"
                 : "=r"(r0), "=r"(r1), "=r"(r2), "=r"(r3) : "r"(addr));
}
__device__ __forceinline__ void ldsm_x4_t(uint32_t& r0, uint32_t& r1,
                                          uint32_t& r2, uint32_t& r3, uint32_t addr) {
    asm volatile("ldmatrix.sync.aligned.m8n8.x4.trans.shared.b16 {%0,%1,%2,%3}, [%4];"
                 : "=r"(r0), "=r"(r1), "=r"(r2), "=r"(r3) : "r"(addr));
}
__device__ __forceinline__ void mma16816(float* d,
                                         uint32_t a0, uint32_t a1, uint32_t a2, uint32_t a3,
                                         uint32_t b0, uint32_t b1) {
    asm volatile("mma.sync.aligned.m16n8k16.row.col.f32.bf16.bf16.f32 "
                 "{%0,%1,%2,%3}, {%4,%5,%6,%7}, {%8,%9}, {%0,%1,%2,%3};"
                 : "+f"(d[0]), "+f"(d[1]), "+f"(d[2]), "+f"(d[3])
                 : "r"(a0), "r"(a1), "r"(a2), "r"(a3), "r"(b0), "r"(b1));
}

// ================= scratch =================
__device__ float    g_Pt[(size_t)NMAX * C1];     // fp32 planes (gemm2)
__device__ float    g_Pb[(size_t)NMAX * C1];
__device__ uint32_t g_PtH[(size_t)NMAX * 128];   // bf16x2 planes (stats1)
__device__ uint32_t g_PbH[(size_t)NMAX * 128];
__device__ float    g_Y2[(size_t)EMAX * C2];
__device__ float    g_s1[2 * C1];
__device__ float    g_mr1[2 * C1];
__device__ float    g_s2[2 * C2];
__device__ float    g_mr2[2 * C2];
__device__ int      g_idx64;

// ================= pre =================
__global__ void k_pre(const int* __restrict__ ei_words)
{
    int gid = blockIdx.x * blockDim.x + threadIdx.x;
    if (gid == 0) {
        int orv = 0;
        #pragma unroll
        for (int i = 1; i < 32; i += 2) orv |= ei_words[i];
        g_idx64 = (orv == 0) ? 1 : 0;
    }
    if (gid < 2 * C1) g_s1[gid] = 0.0f;
    if (gid < 2 * C2) g_s2[gid] = 0.0f;
}

// ================= node projection (fp32 SIMT) =================
__global__ __launch_bounds__(256, 1)
void k_proj(const float* __restrict__ emb,
            const float* __restrict__ W1,
            const float* __restrict__ b1,
            int N)
{
    extern __shared__ float sm[];
    float* Ws = sm;                 // 128*256
    float* As = sm + K1DIM * C1;    // 32*64

    const int tid = threadIdx.x;
    for (int i = tid; i < K1DIM * C1 / 4; i += blockDim.x)
        ((float4*)Ws)[i] = ((const float4*)W1)[i];

    const int tx = tid & 31;
    const int ty = tid >> 5;

    float biasReg[8];
    #pragma unroll
    for (int c = 0; c < 8; c++) biasReg[c] = b1[tx * 8 + c];

    __syncthreads();

    const int nTiles = (N + 31) / 32;
    for (int tile = blockIdx.x; tile < nTiles; tile += gridDim.x) {
        const int base = tile * 32;
        for (int i = tid; i < 32 * 16; i += blockDim.x) {
            const int r = i >> 4, q = i & 15;
            const int n = base + r;
            float4 v = make_float4(0.f, 0.f, 0.f, 0.f);
            if (n < N) v = ((const float4*)(emb + (size_t)n * H))[q];
            ((float4*)(As + r * H))[q] = v;
        }
        __syncthreads();

        const float* Arow = As + (ty * 4) * H;

        #define PROJ_PASS(ROWOFF, DST, DSTH, ADDBIAS)                         \
        {                                                                     \
            float acc[4][8];                                                  \
            _Pragma("unroll")                                                 \
            for (int r = 0; r < 4; r++)                                       \
                _Pragma("unroll")                                             \
                for (int c = 0; c < 8; c++) acc[r][c] = 0.0f;                 \
            _Pragma("unroll 4")                                               \
            for (int k = 0; k < H; k++) {                                     \
                const float4 w0 = *((const float4*)(Ws + (ROWOFF + k) * C1 + tx * 8));     \
                const float4 w1 = *((const float4*)(Ws + (ROWOFF + k) * C1 + tx * 8 + 4)); \
                const float a0 = Arow[k];                                     \
                const float a1 = Arow[H + k];                                 \
                const float a2 = Arow[2 * H + k];                             \
                const float a3 = Arow[3 * H + k];                             \
                _Pragma("unroll")                                             \
                for (int r = 0; r < 4; r++) {                                 \
                    const float a = (r == 0) ? a0 : (r == 1) ? a1 : (r == 2) ? a2 : a3; \
                    acc[r][0] += a * w0.x; acc[r][1] += a * w0.y;             \
                    acc[r][2] += a * w0.z; acc[r][3] += a * w0.w;             \
                    acc[r][4] += a * w1.x; acc[r][5] += a * w1.y;             \
                    acc[r][6] += a * w1.z; acc[r][7] += a * w1.w;             \
                }                                                             \
            }                                                                 \
            _Pragma("unroll")                                                 \
            for (int r = 0; r < 4; r++) {                                     \
                const int n = base + ty * 4 + r;                              \
                if (n < N) {                                                  \
                    float v[8];                                               \
                    _Pragma("unroll")                                         \
                    for (int c = 0; c < 8; c++)                               \
                        v[c] = acc[r][c] + (ADDBIAS ? biasReg[c] : 0.0f);     \
                    float4* dst = (float4*)(DST + (size_t)n * C1 + tx * 8);   \
                    dst[0] = make_float4(v[0], v[1], v[2], v[3]);             \
                    dst[1] = make_float4(v[4], v[5], v[6], v[7]);             \
                    const __nv_bfloat162 p01 = __floats2bfloat162_rn(v[0], v[1]); \
                    const __nv_bfloat162 p23 = __floats2bfloat162_rn(v[2], v[3]); \
                    const __nv_bfloat162 p45 = __floats2bfloat162_rn(v[4], v[5]); \
                    const __nv_bfloat162 p67 = __floats2bfloat162_rn(v[6], v[7]); \
                    uint4 u;                                                  \
                    u.x = *(const uint32_t*)&p01; u.y = *(const uint32_t*)&p23; \
                    u.z = *(const uint32_t*)&p45; u.w = *(const uint32_t*)&p67; \
                    ((uint4*)(DSTH + (size_t)n * 128))[tx] = u;               \
                }                                                             \
            }                                                                 \
        }
        PROJ_PASS(0,  g_Pt, g_PtH, 1)
        PROJ_PASS(64, g_Pb, g_PbH, 0)
        #undef PROJ_PASS
        __syncthreads();
    }
}

// ================= layer-1 stats (bf16 planes, half traffic) =============
__global__ __launch_bounds__(256)
void k_stats1(const void* __restrict__ ei, int E)
{
    const long long* ei64 = (const long long*)ei;
    const int*       ei32 = (const int*)ei;
    const int is64 = g_idx64;
    const int c2   = threadIdx.x & 127;
    const int half = threadIdx.x >> 7;

    float s0 = 0.f, q0 = 0.f, s1 = 0.f, q1 = 0.f;
    const int stride = gridDim.x * 8;
    for (int e0 = blockIdx.x * 8 + half * 4; e0 < E; e0 += stride) {
        uint32_t ta[4], tb[4];
        int nv = 0;
        #pragma unroll
        for (int j = 0; j < 4; j++) {
            const int e = e0 + j;
            if (e < E) {
                const long long ci = is64 ? ei64[e]     : (long long)ei32[e];
                const long long ri = is64 ? ei64[E + e] : (long long)ei32[E + e];
                ta[j] = __ldg(g_PtH + ci * 128 + c2);
                tb[j] = __ldg(g_PbH + ri * 128 + c2);
                nv = j + 1;
            }
        }
        #pragma unroll
        for (int j = 0; j < 4; j++) {
            if (j < nv) {
                const float2 af = __bfloat1622float2(*(const __nv_bfloat162*)&ta[j]);
                const float2 bf = __bfloat1622float2(*(const __nv_bfloat162*)&tb[j]);
                const float v0 = af.x + bf.x;
                const float v1 = af.y + bf.y;
                s0 += v0; q0 += v0 * v0;
                s1 += v1; q1 += v1 * v1;
            }
        }
    }
    atomicAdd(&g_s1[2 * c2],          s0);
    atomicAdd(&g_s1[2 * c2 + 1],      s1);
    atomicAdd(&g_s1[C1 + 2 * c2],     q0);
    atomicAdd(&g_s1[C1 + 2 * c2 + 1], q1);
}

__global__ void k_fin1(float invE)
{
    const int c = threadIdx.x;
    if (c < C1) {
        const float m   = g_s1[c] * invE;
        const float var = g_s1[C1 + c] * invE - m * m;
        g_mr1[c]      = m;
        g_mr1[C1 + c] = rsqrtf(var + EPSV);
    }
}

// ================= layer 2: pipelined bf16-split warp MMA ================
// 512 threads = 16 warps. Tile = 64 edges x 64 cols, K = 256, double-
// buffered A. Warp: wm = wid&3 -> rows [wm*16,+16); wn = wid>>2 -> cols
// [wn*16,+16). Passes: Ah@Bh + Ah@Bl + Al@Bh. Pipeline: gather t+1 into
// regs, MMA t between the LDG issue and the STS, one barrier per tile.
#define TR 64
#define ASTR 264               // A smem row stride (bf16), 8-elem pad
#define BSTR 72                // B smem row stride (bf16), 8-elem pad
#define ABUF (TR * ASTR * 2)   // 33792 B per plane per buffer
#define BPLANE (C1 * BSTR * 2) // 36864 B
#define OFF_B (4 * ABUF)       // 135168
#define SMT_G2 (OFF_B + 2 * BPLANE)   // 208896

__device__ __forceinline__ void cvt_split4(float4 a, float4 b, float4 ms, float4 rs,
                                           uint32_t& h01, uint32_t& h23,
                                           uint32_t& l01, uint32_t& l23)
{
    const float v0 = fmaxf(0.f, (a.x + b.x - ms.x) * rs.x);
    const float v1 = fmaxf(0.f, (a.y + b.y - ms.y) * rs.y);
    const float v2 = fmaxf(0.f, (a.z + b.z - ms.z) * rs.z);
    const float v3 = fmaxf(0.f, (a.w + b.w - ms.w) * rs.w);
    const __nv_bfloat162 H01 = __floats2bfloat162_rn(v0, v1);
    const __nv_bfloat162 H23 = __floats2bfloat162_rn(v2, v3);
    const float r0 = v0 - __bfloat162float(__low2bfloat16(H01));
    const float r1 = v1 - __bfloat162float(__high2bfloat16(H01));
    const float r2 = v2 - __bfloat162float(__low2bfloat16(H23));
    const float r3 = v3 - __bfloat162float(__high2bfloat16(H23));
    const __nv_bfloat162 L01 = __floats2bfloat162_rn(r0, r1);
    const __nv_bfloat162 L23 = __floats2bfloat162_rn(r2, r3);
    h01 = *(const uint32_t*)&H01; h23 = *(const uint32_t*)&H23;
    l01 = *(const uint32_t*)&L01; l23 = *(const uint32_t*)&L23;
}

__global__ __launch_bounds__(512, 1)
void k_gemm2_mma(const void* __restrict__ ei,
                 const float* __restrict__ W2,
                 const float* __restrict__ b2,
                 int E)
{
    extern __shared__ char smraw[];
    const uint32_t smBase = smem_u32(smraw);
    __nv_bfloat16* Bh = (__nv_bfloat16*)(smraw + OFF_B);
    __nv_bfloat16* Bl = (__nv_bfloat16*)(smraw + OFF_B + BPLANE);
    const uint32_t BhA = smBase + OFF_B;
    const uint32_t BlA = BhA + BPLANE;

    const int tid  = threadIdx.x;
    const int lane = tid & 31;
    const int wid  = tid >> 5;

    // --- build W2^T hi/lo planes ---
    for (int i = tid; i < C1 * C2; i += 512) {
        const int k = i >> 6, n = i & 63;
        const float w = W2[k * C2 + n];
        const __nv_bfloat16 hh = __float2bfloat16(w);
        const __nv_bfloat16 ll = __float2bfloat16(w - __bfloat162float(hh));
        Bh[k * BSTR + n] = hh;
        Bl[k * BSTR + n] = ll;
    }

    const long long* ei64 = (const long long*)ei;
    const int*       ei32 = (const int*)ei;
    const int is64 = g_idx64;

    // loop-invariant per-thread normalization params (q = tid&63 fixed)
    const int q  = tid & 63;
    const int rq = tid >> 6;                 // base row 0..7
    const float4 ms4 = ((const float4*)g_mr1)[q];
    const float4 rs4 = ((const float4*)(g_mr1 + C1))[q];

    const int wm = wid & 3;          // row group (16 rows)
    const int wn = wid >> 2;         // col group (16 cols)
    const int tg = lane & 3;
    const uint32_t aOff = (uint32_t)((wm * 16 + (lane & 15)) * ASTR + (lane >> 4) * 8) * 2;
    const uint32_t bOff = (uint32_t)(((lane & 7) + ((lane >> 3) & 1) * 8) * BSTR
                                     + wn * 16 + (lane >> 4) * 8) * 2;

    float bias[4];
    bias[0] = b2[wn * 16 + tg * 2];
    bias[1] = b2[wn * 16 + tg * 2 + 1];
    bias[2] = b2[wn * 16 + 8 + tg * 2];
    bias[3] = b2[wn * 16 + 8 + tg * 2 + 1];

    float sSum[4] = {0.f, 0.f, 0.f, 0.f};
    float sSq[4]  = {0.f, 0.f, 0.f, 0.f};

    const int nTiles = (E + TR - 1) / TR;
    const int stride = gridDim.x;

    // helper lambdas -------------------------------------------------------
    auto gatherRow = [&](int e, float4& a, float4& b) {
        a = make_float4(0.f, 0.f, 0.f, 0.f);
        b = make_float4(0.f, 0.f, 0.f, 0.f);
        if (e < E) {
            const long long ci = is64 ? ei64[e]     : (long long)ei32[e];
            const long long ri = is64 ? ei64[E + e] : (long long)ei32[E + e];
            a = ((const float4*)(g_Pt + ci * C1))[q];
            b = ((const float4*)(g_Pb + ri * C1))[q];
        }
    };
    auto stsRow = [&](char* bAh, char* bAl, int r,
                      uint32_t h01, uint32_t h23, uint32_t l01, uint32_t l23) {
        uint32_t* ah = (uint32_t*)(bAh + r * (ASTR * 2));
        uint32_t* al = (uint32_t*)(bAl + r * (ASTR * 2));
        ah[q * 2] = h01; ah[q * 2 + 1] = h23;
        al[q * 2] = l01; al[q * 2 + 1] = l23;
    };

    // prologue: full build of first tile into buffer 0
    if (blockIdx.x < nTiles) {
        char* bAh = smraw;
        char* bAl = smraw + ABUF;
        #pragma unroll
        for (int k = 0; k < 8; k++) {
            const int r = rq + k * 8;
            float4 a, b;
            gatherRow(blockIdx.x * TR + r, a, b);
            uint32_t h01, h23, l01, l23;
            cvt_split4(a, b, ms4, rs4, h01, h23, l01, l23);
            stsRow(bAh, bAl, r, h01, h23, l01, l23);
        }
    }
    __syncthreads();

    int cur = 0;
    for (int t = blockIdx.x; t < nTiles; t += stride) {
        const int nt = t + stride;
        const bool pf = (nt < nTiles);
        const uint32_t curAh = smBase + cur * 2 * ABUF;
        const uint32_t curAl = curAh + ABUF;
        char* nxtAh = smraw + (cur ^ 1) * 2 * ABUF;
        char* nxtAl = nxtAh + ABUF;

        float acc[2][4];
        #pragma unroll
        for (int nb = 0; nb < 2; nb++)
            #pragma unroll
            for (int c = 0; c < 4; c++) acc[nb][c] = 0.0f;

        #define MMA_PASS(APLANE, BPLANEADDR)                                  \
        {                                                                     \
            const uint32_t aB = (APLANE) + aOff;                              \
            const uint32_t bB = (BPLANEADDR) + bOff;                          \
            _Pragma("unroll")                                                 \
            for (int kb = 0; kb < 16; kb++) {                                 \
                uint32_t a0, a1, a2, a3, b0, b1, b2_, b3_;                    \
                ldsm_x4(a0, a1, a2, a3, aB + kb * 32);                        \
                ldsm_x4_t(b0, b1, b2_, b3_, bB + kb * (16 * BSTR * 2));       \
                mma16816(acc[0], a0, a1, a2, a3, b0, b1);                     \
                mma16816(acc[1], a0, a1, a2, a3, b2_, b3_);                   \
            }                                                                 \
        }

        // -- gather group A for next tile (LDG latency hidden by pass 0) --
        float4 pa[4], pb[4];
        if (pf) {
            #pragma unroll
            for (int k = 0; k < 4; k++)
                gatherRow(nt * TR + rq + k * 8, pa[k], pb[k]);
        }

        MMA_PASS(curAh, BhA)   // pass 0: Ah @ Bh

        if (pf) {
            #pragma unroll
            for (int k = 0; k < 4; k++) {
                uint32_t h01, h23, l01, l23;
                cvt_split4(pa[k], pb[k], ms4, rs4, h01, h23, l01, l23);
                stsRow(nxtAh, nxtAl, rq + k * 8, h01, h23, l01, l23);
            }
            #pragma unroll
            for (int k = 0; k < 4; k++)
                gatherRow(nt * TR + rq + (k + 4) * 8, pa[k], pb[k]);
        }

        MMA_PASS(curAh, BlA)   // pass 1: Ah @ Bl

        if (pf) {
            #pragma unroll
            for (int k = 0; k < 4; k++) {
                uint32_t h01, h23, l01, l23;
                cvt_split4(pa[k], pb[k], ms4, rs4, h01, h23, l01, l23);
                stsRow(nxtAh, nxtAl, rq + (k + 4) * 8, h01, h23, l01, l23);
            }
        }

        MMA_PASS(curAl, BhA)   // pass 2: Al @ Bh
        #undef MMA_PASS

        // ---- epilogue: +bias, store Y2, accumulate stats2 ----
        {
            const int g  = lane >> 2;
            const int e0 = t * TR + wm * 16 + g;
            const int e1 = e0 + 8;
            float* y0 = g_Y2 + (size_t)e0 * C2;
            float* y1 = g_Y2 + (size_t)e1 * C2;
            #pragma unroll
            for (int nb = 0; nb < 2; nb++) {
                const int c = wn * 16 + nb * 8 + tg * 2;
                const float bx = bias[nb * 2], by = bias[nb * 2 + 1];
                if (e0 < E) {
                    const float ox = acc[nb][0] + bx;
                    const float oy = acc[nb][1] + by;
                    *(float2*)(y0 + c) = make_float2(ox, oy);
                    sSum[nb * 2 + 0] += ox; sSq[nb * 2 + 0] += ox * ox;
                    sSum[nb * 2 + 1] += oy; sSq[nb * 2 + 1] += oy * oy;
                }
                if (e1 < E) {
                    const float ox = acc[nb][2] + bx;
                    const float oy = acc[nb][3] + by;
                    *(float2*)(y1 + c) = make_float2(ox, oy);
                    sSum[nb * 2 + 0] += ox; sSq[nb * 2 + 0] += ox * ox;
                    sSum[nb * 2 + 1] += oy; sSq[nb * 2 + 1] += oy * oy;
                }
            }
        }
        __syncthreads();
        cur ^= 1;
    }

    // ---- stats2 reduction: smem scratch, then global atomics ----
    float* sS = (float*)smraw;       // 64 floats
    float* sQ = sS + 64;             // 64 floats
    __syncthreads();
    if (tid < 128) sS[tid] = 0.f;
    __syncthreads();
    #pragma unroll
    for (int nb = 0; nb < 2; nb++) {
        const int c = wn * 16 + nb * 8 + tg * 2;
        atomicAdd(&sS[c],     sSum[nb * 2 + 0]);
        atomicAdd(&sS[c + 1], sSum[nb * 2 + 1]);
        atomicAdd(&sQ[c],     sSq[nb * 2 + 0]);
        atomicAdd(&sQ[c + 1], sSq[nb * 2 + 1]);
    }
    __syncthreads();
    if (tid < C2) {
        atomicAdd(&g_s2[tid],      sS[tid]);
        atomicAdd(&g_s2[C2 + tid], sQ[tid]);
    }
}

__global__ void k_fin2(float invE)
{
    const int c = threadIdx.x;
    if (c < C2) {
        const float m   = g_s2[c] * invE;
        const float var = g_s2[C2 + c] * invE - m * m;
        g_mr2[c]      = m;
        g_mr2[C2 + c] = rsqrtf(var + EPSV);
    }
}

// ================= layer 3 =================
__global__ void k_out(const float* __restrict__ W3,
                      const float* __restrict__ b3,
                      float* __restrict__ out,
                      int E)
{
    __shared__ float w[C2], m[C2], rs[C2];
    const int tid = threadIdx.x;
    if (tid < C2) {
        w[tid]  = W3[tid];
        m[tid]  = g_mr2[tid];
        rs[tid] = g_mr2[C2 + tid];
    }
    __syncthreads();

    const int lane = tid & 31;
    const int warp = tid >> 5;
    const int e = blockIdx.x * (blockDim.x >> 5) + warp;
    if (e >= E) return;

    const float2 y = ((const float2*)(g_Y2 + (size_t)e * C2))[lane];
    const int c = lane * 2;
    float p = fmaxf(0.f, (y.x - m[c])     * rs[c])     * w[c]
            + fmaxf(0.f, (y.y - m[c + 1]) * rs[c + 1]) * w[c + 1];
    #pragma unroll
    for (int o = 16; o > 0; o >>= 1) p += __shfl_down_sync(0xffffffffu, p, o);
    if (lane == 0) out[e] = p + b3[0];
}

// ================= launch =================
extern "C" void kernel_launch(void* const* d_in, const int* in_sizes, int n_in,
                              void* d_out, int out_size)
{
    const float* emb = (const float*)d_in[0];
    const void*  ei  = d_in[1];
    const float* W1  = (const float*)d_in[2];
    const float* b1  = (const float*)d_in[3];
    const float* W2  = (const float*)d_in[4];
    const float* b2  = (const float*)d_in[5];
    const float* W3  = (const float*)d_in[6];
    const float* b3  = (const float*)d_in[7];
    float* out = (float*)d_out;

    const int N = in_sizes[0] / H;
    const int E = in_sizes[1] / 2;

    int dev = 0;
    cudaGetDevice(&dev);
    int nsm = 148;
    cudaDeviceGetAttribute(&nsm, cudaDevAttrMultiProcessorCount, dev);

    const int smP = (K1DIM * C1 + 32 * H) * (int)sizeof(float);   // 139264
    cudaFuncSetAttribute(k_proj,      cudaFuncAttributeMaxDynamicSharedMemorySize, smP);
    cudaFuncSetAttribute(k_gemm2_mma, cudaFuncAttributeMaxDynamicSharedMemorySize, SMT_G2);

    const int nTiles = (E + TR - 1) / TR;
    const int g2 = nsm < nTiles ? nsm : nTiles;

    k_pre<<<2, 256>>>((const int*)ei);
    k_proj<<<nsm, 256, smP>>>(emb, W1, b1, N);
    k_stats1<<<nsm * 8, 256>>>(ei, E);
    k_fin1<<<1, 256>>>(1.0f / (float)E);
    k_gemm2_mma<<<g2, 512, SMT_G2>>>(ei, W2, b2, E);
    k_fin2<<<1, 64>>>(1.0f / (float)E);
    k_out<<<(E + 7) / 8, 256>>>(W3, b3, out, E);
}

// round 10
// speedup vs baseline: 5.7402x; 1.1947x over previous
#include <cuda_runtime.h>
#include <cuda_bf16.h>
#include <cuda_fp16.h>
#include <cstdint>

#define NMAX 65536
#define EMAX 800000
#define K1DIM 128   // 2H
#define C1 256      // 4H
#define C2 64       // H
#define H  64
#define EPSV 1e-5f

// ---- warp MMA helpers (plain sm_103-compatible: no tcgen05) -------------
__device__ __forceinline__ uint32_t smem_u32(const void* p) {
    uint32_t a;
    asm("{ .reg .u64 t; cvta.to.shared.u64 t, %1; cvt.u32.u64 %0, t; }"
        : "=r"(a) : "l"(p));
    return a;
}
__device__ __forceinline__ void ldsm_x4(uint32_t& r0, uint32_t& r1,
                                        uint32_t& r2, uint32_t& r3, uint32_t addr) {
    asm volatile("ldmatrix.sync.aligned.m8n8.x4.shared.b16 {%0,%1,%2,%3}, [%4];"
                 : "=r"(r0), "=r"(r1), "=r"(r2), "=r"(r3) : "r"(addr));
}
__device__ __forceinline__ void ldsm_x4_t(uint32_t& r0, uint32_t& r1,
                                          uint32_t& r2, uint32_t& r3, uint32_t addr) {
    asm volatile("ldmatrix.sync.aligned.m8n8.x4.trans.shared.b16 {%0,%1,%2,%3}, [%4];"
                 : "=r"(r0), "=r"(r1), "=r"(r2), "=r"(r3) : "r"(addr));
}
__device__ __forceinline__ void mma16816h(float* d,
                                          uint32_t a0, uint32_t a1, uint32_t a2, uint32_t a3,
                                          uint32_t b0, uint32_t b1) {
    asm volatile("mma.sync.aligned.m16n8k16.row.col.f32.f16.f16.f32 "
                 "{%0,%1,%2,%3}, {%4,%5,%6,%7}, {%8,%9}, {%0,%1,%2,%3};"
                 : "+f"(d[0]), "+f"(d[1]), "+f"(d[2]), "+f"(d[3])
                 : "r"(a0), "r"(a1), "r"(a2), "r"(a3), "r"(b0), "r"(b1));
}

// ================= scratch =================
__device__ float    g_Pt[(size_t)NMAX * C1];     // fp32 planes (gemm2)
__device__ float    g_Pb[(size_t)NMAX * C1];
__device__ uint32_t g_PtH[(size_t)NMAX * 128];   // bf16x2 planes (stats1)
__device__ uint32_t g_PbH[(size_t)NMAX * 128];
__device__ float    g_Y2[(size_t)EMAX * C2];
__device__ float    g_s1[2 * C1];
__device__ float    g_mr1[2 * C1];
__device__ float    g_s2[2 * C2];
__device__ float    g_mr2[2 * C2];
__device__ int      g_idx64;

// ================= pre =================
__global__ void k_pre(const int* __restrict__ ei_words)
{
    int gid = blockIdx.x * blockDim.x + threadIdx.x;
    if (gid == 0) {
        int orv = 0;
        #pragma unroll
        for (int i = 1; i < 32; i += 2) orv |= ei_words[i];
        g_idx64 = (orv == 0) ? 1 : 0;
    }
    if (gid < 2 * C1) g_s1[gid] = 0.0f;
    if (gid < 2 * C2) g_s2[gid] = 0.0f;
}

// ================= node projection (fp32 SIMT) =================
__global__ __launch_bounds__(256, 1)
void k_proj(const float* __restrict__ emb,
            const float* __restrict__ W1,
            const float* __restrict__ b1,
            int N)
{
    extern __shared__ float sm[];
    float* Ws = sm;                 // 128*256
    float* As = sm + K1DIM * C1;    // 32*64

    const int tid = threadIdx.x;
    for (int i = tid; i < K1DIM * C1 / 4; i += blockDim.x)
        ((float4*)Ws)[i] = ((const float4*)W1)[i];

    const int tx = tid & 31;
    const int ty = tid >> 5;

    float biasReg[8];
    #pragma unroll
    for (int c = 0; c < 8; c++) biasReg[c] = b1[tx * 8 + c];

    __syncthreads();

    const int nTiles = (N + 31) / 32;
    for (int tile = blockIdx.x; tile < nTiles; tile += gridDim.x) {
        const int base = tile * 32;
        for (int i = tid; i < 32 * 16; i += blockDim.x) {
            const int r = i >> 4, q = i & 15;
            const int n = base + r;
            float4 v = make_float4(0.f, 0.f, 0.f, 0.f);
            if (n < N) v = ((const float4*)(emb + (size_t)n * H))[q];
            ((float4*)(As + r * H))[q] = v;
        }
        __syncthreads();

        const float* Arow = As + (ty * 4) * H;

        #define PROJ_PASS(ROWOFF, DST, DSTH, ADDBIAS)                         \
        {                                                                     \
            float acc[4][8];                                                  \
            _Pragma("unroll")                                                 \
            for (int r = 0; r < 4; r++)                                       \
                _Pragma("unroll")                                             \
                for (int c = 0; c < 8; c++) acc[r][c] = 0.0f;                 \
            _Pragma("unroll 4")                                               \
            for (int k = 0; k < H; k++) {                                     \
                const float4 w0 = *((const float4*)(Ws + (ROWOFF + k) * C1 + tx * 8));     \
                const float4 w1 = *((const float4*)(Ws + (ROWOFF + k) * C1 + tx * 8 + 4)); \
                const float a0 = Arow[k];                                     \
                const float a1 = Arow[H + k];                                 \
                const float a2 = Arow[2 * H + k];                             \
                const float a3 = Arow[3 * H + k];                             \
                _Pragma("unroll")                                             \
                for (int r = 0; r < 4; r++) {                                 \
                    const float a = (r == 0) ? a0 : (r == 1) ? a1 : (r == 2) ? a2 : a3; \
                    acc[r][0] += a * w0.x; acc[r][1] += a * w0.y;             \
                    acc[r][2] += a * w0.z; acc[r][3] += a * w0.w;             \
                    acc[r][4] += a * w1.x; acc[r][5] += a * w1.y;             \
                    acc[r][6] += a * w1.z; acc[r][7] += a * w1.w;             \
                }                                                             \
            }                                                                 \
            _Pragma("unroll")                                                 \
            for (int r = 0; r < 4; r++) {                                     \
                const int n = base + ty * 4 + r;                              \
                if (n < N) {                                                  \
                    float v[8];                                               \
                    _Pragma("unroll")                                         \
                    for (int c = 0; c < 8; c++)                               \
                        v[c] = acc[r][c] + (ADDBIAS ? biasReg[c] : 0.0f);     \
                    float4* dst = (float4*)(DST + (size_t)n * C1 + tx * 8);   \
                    dst[0] = make_float4(v[0], v[1], v[2], v[3]);             \
                    dst[1] = make_float4(v[4], v[5], v[6], v[7]);             \
                    const __nv_bfloat162 p01 = __floats2bfloat162_rn(v[0], v[1]); \
                    const __nv_bfloat162 p23 = __floats2bfloat162_rn(v[2], v[3]); \
                    const __nv_bfloat162 p45 = __floats2bfloat162_rn(v[4], v[5]); \
                    const __nv_bfloat162 p67 = __floats2bfloat162_rn(v[6], v[7]); \
                    uint4 u;                                                  \
                    u.x = *(const uint32_t*)&p01; u.y = *(const uint32_t*)&p23; \
                    u.z = *(const uint32_t*)&p45; u.w = *(const uint32_t*)&p67; \
                    ((uint4*)(DSTH + (size_t)n * 128))[tx] = u;               \
                }                                                             \
            }                                                                 \
        }
        PROJ_PASS(0,  g_Pt, g_PtH, 1)
        PROJ_PASS(64, g_Pb, g_PbH, 0)
        #undef PROJ_PASS
        __syncthreads();
    }
}

// ================= layer-1 stats (bf16 planes, half traffic) =============
__global__ __launch_bounds__(256)
void k_stats1(const void* __restrict__ ei, int E)
{
    const long long* ei64 = (const long long*)ei;
    const int*       ei32 = (const int*)ei;
    const int is64 = g_idx64;
    const int c2   = threadIdx.x & 127;
    const int half = threadIdx.x >> 7;

    float s0 = 0.f, q0 = 0.f, s1 = 0.f, q1 = 0.f;
    const int stride = gridDim.x * 8;
    for (int e0 = blockIdx.x * 8 + half * 4; e0 < E; e0 += stride) {
        uint32_t ta[4], tb[4];
        int nv = 0;
        #pragma unroll
        for (int j = 0; j < 4; j++) {
            const int e = e0 + j;
            if (e < E) {
                const long long ci = is64 ? ei64[e]     : (long long)ei32[e];
                const long long ri = is64 ? ei64[E + e] : (long long)ei32[E + e];
                ta[j] = __ldg(g_PtH + ci * 128 + c2);
                tb[j] = __ldg(g_PbH + ri * 128 + c2);
                nv = j + 1;
            }
        }
        #pragma unroll
        for (int j = 0; j < 4; j++) {
            if (j < nv) {
                const float2 af = __bfloat1622float2(*(const __nv_bfloat162*)&ta[j]);
                const float2 bf = __bfloat1622float2(*(const __nv_bfloat162*)&tb[j]);
                const float v0 = af.x + bf.x;
                const float v1 = af.y + bf.y;
                s0 += v0; q0 += v0 * v0;
                s1 += v1; q1 += v1 * v1;
            }
        }
    }
    atomicAdd(&g_s1[2 * c2],          s0);
    atomicAdd(&g_s1[2 * c2 + 1],      s1);
    atomicAdd(&g_s1[C1 + 2 * c2],     q0);
    atomicAdd(&g_s1[C1 + 2 * c2 + 1], q1);
}

__global__ void k_fin1(float invE)
{
    const int c = threadIdx.x;
    if (c < C1) {
        const float m   = g_s1[c] * invE;
        const float var = g_s1[C1 + c] * invE - m * m;
        g_mr1[c]      = m;
        g_mr1[C1 + c] = rsqrtf(var + EPSV);
    }
}

// ================= layer 2: pipelined fp16-split warp MMA ================
// 512 threads = 16 warps. Tile = 64 edges x 64 cols, K = 256, double-
// buffered A (hi+lo fp16 planes), single fp16 B plane (W2^T).
// y2 = Ah@B + Al@B into the SAME accumulator; B frags loaded once per
// k-step and reused by both A planes.
#define TR 64
#define ASTR 264               // A smem row stride (fp16), 8-elem pad
#define BSTR 72                // B smem row stride (fp16), 8-elem pad
#define ABUF (TR * ASTR * 2)   // 33792 B per plane per buffer
#define BPLANE (C1 * BSTR * 2) // 36864 B
#define OFF_B (4 * ABUF)       // 135168
#define SMT_G2 (OFF_B + BPLANE)   // 172032

__device__ __forceinline__ void cvt_split4h(float4 a, float4 b, float4 ms, float4 rs,
                                            uint32_t& h01, uint32_t& h23,
                                            uint32_t& l01, uint32_t& l23)
{
    const float v0 = fmaxf(0.f, (a.x + b.x - ms.x) * rs.x);
    const float v1 = fmaxf(0.f, (a.y + b.y - ms.y) * rs.y);
    const float v2 = fmaxf(0.f, (a.z + b.z - ms.z) * rs.z);
    const float v3 = fmaxf(0.f, (a.w + b.w - ms.w) * rs.w);
    const __half2 H01 = __floats2half2_rn(v0, v1);
    const __half2 H23 = __floats2half2_rn(v2, v3);
    const float r0 = v0 - __low2float(H01);
    const float r1 = v1 - __high2float(H01);
    const float r2 = v2 - __low2float(H23);
    const float r3 = v3 - __high2float(H23);
    const __half2 L01 = __floats2half2_rn(r0, r1);
    const __half2 L23 = __floats2half2_rn(r2, r3);
    h01 = *(const uint32_t*)&H01; h23 = *(const uint32_t*)&H23;
    l01 = *(const uint32_t*)&L01; l23 = *(const uint32_t*)&L23;
}

__global__ __launch_bounds__(512, 1)
void k_gemm2_mma(const void* __restrict__ ei,
                 const float* __restrict__ W2,
                 const float* __restrict__ b2,
                 int E)
{
    extern __shared__ char smraw[];
    const uint32_t smBase = smem_u32(smraw);
    __half* Bh = (__half*)(smraw + OFF_B);
    const uint32_t BhA = smBase + OFF_B;

    const int tid  = threadIdx.x;
    const int lane = tid & 31;
    const int wid  = tid >> 5;

    // --- build W2^T fp16 plane ---
    for (int i = tid; i < C1 * C2; i += 512) {
        const int k = i >> 6, n = i & 63;
        Bh[k * BSTR + n] = __float2half(W2[k * C2 + n]);
    }

    const long long* ei64 = (const long long*)ei;
    const int*       ei32 = (const int*)ei;
    const int is64 = g_idx64;

    // loop-invariant per-thread normalization params (q = tid&63 fixed)
    const int q  = tid & 63;
    const int rq = tid >> 6;                 // base row 0..7
    const float4 ms4 = ((const float4*)g_mr1)[q];
    const float4 rs4 = ((const float4*)(g_mr1 + C1))[q];

    const int wm = wid & 3;          // row group (16 rows)
    const int wn = wid >> 2;         // col group (16 cols)
    const int tg = lane & 3;
    const uint32_t aOff = (uint32_t)((wm * 16 + (lane & 15)) * ASTR + (lane >> 4) * 8) * 2;
    const uint32_t bOff = (uint32_t)(((lane & 7) + ((lane >> 3) & 1) * 8) * BSTR
                                     + wn * 16 + (lane >> 4) * 8) * 2;

    float bias[4];
    bias[0] = b2[wn * 16 + tg * 2];
    bias[1] = b2[wn * 16 + tg * 2 + 1];
    bias[2] = b2[wn * 16 + 8 + tg * 2];
    bias[3] = b2[wn * 16 + 8 + tg * 2 + 1];

    float sSum[4] = {0.f, 0.f, 0.f, 0.f};
    float sSq[4]  = {0.f, 0.f, 0.f, 0.f};

    const int nTiles = (E + TR - 1) / TR;
    const int stride = gridDim.x;

    auto gatherRow = [&](int e, float4& a, float4& b) {
        a = make_float4(0.f, 0.f, 0.f, 0.f);
        b = make_float4(0.f, 0.f, 0.f, 0.f);
        if (e < E) {
            const long long ci = is64 ? ei64[e]     : (long long)ei32[e];
            const long long ri = is64 ? ei64[E + e] : (long long)ei32[E + e];
            a = ((const float4*)(g_Pt + ci * C1))[q];
            b = ((const float4*)(g_Pb + ri * C1))[q];
        }
    };
    auto stsRow = [&](char* bAh, char* bAl, int r,
                      uint32_t h01, uint32_t h23, uint32_t l01, uint32_t l23) {
        uint32_t* ah = (uint32_t*)(bAh + r * (ASTR * 2));
        uint32_t* al = (uint32_t*)(bAl + r * (ASTR * 2));
        ah[q * 2] = h01; ah[q * 2 + 1] = h23;
        al[q * 2] = l01; al[q * 2 + 1] = l23;
    };

    // prologue: full build of first tile into buffer 0
    if (blockIdx.x < nTiles) {
        char* bAh = smraw;
        char* bAl = smraw + ABUF;
        #pragma unroll
        for (int k = 0; k < 8; k++) {
            const int r = rq + k * 8;
            float4 a, b;
            gatherRow(blockIdx.x * TR + r, a, b);
            uint32_t h01, h23, l01, l23;
            cvt_split4h(a, b, ms4, rs4, h01, h23, l01, l23);
            stsRow(bAh, bAl, r, h01, h23, l01, l23);
        }
    }
    __syncthreads();

    int cur = 0;
    for (int t = blockIdx.x; t < nTiles; t += stride) {
        const int nt = t + stride;
        const bool pf = (nt < nTiles);
        const uint32_t curAh = smBase + cur * 2 * ABUF;
        const uint32_t curAl = curAh + ABUF;
        char* nxtAh = smraw + (cur ^ 1) * 2 * ABUF;
        char* nxtAl = nxtAh + ABUF;

        float acc[2][4];
        #pragma unroll
        for (int nb = 0; nb < 2; nb++)
            #pragma unroll
            for (int c = 0; c < 4; c++) acc[nb][c] = 0.0f;

        #define MMA_STEP(kb)                                                  \
        {                                                                     \
            uint32_t ah0, ah1, ah2, ah3, al0, al1, al2, al3;                  \
            uint32_t b0, b1, b2_, b3_;                                        \
            ldsm_x4(ah0, ah1, ah2, ah3, curAh + aOff + (kb) * 32);            \
            ldsm_x4(al0, al1, al2, al3, curAl + aOff + (kb) * 32);            \
            ldsm_x4_t(b0, b1, b2_, b3_, BhA + bOff + (kb) * (16 * BSTR * 2)); \
            mma16816h(acc[0], ah0, ah1, ah2, ah3, b0, b1);                    \
            mma16816h(acc[1], ah0, ah1, ah2, ah3, b2_, b3_);                  \
            mma16816h(acc[0], al0, al1, al2, al3, b0, b1);                    \
            mma16816h(acc[1], al0, al1, al2, al3, b2_, b3_);                  \
        }

        // -- gather group A for next tile (LDG latency hidden by MMA 0-7) --
        float4 pa[4], pb[4];
        if (pf) {
            #pragma unroll
            for (int k = 0; k < 4; k++)
                gatherRow(nt * TR + rq + k * 8, pa[k], pb[k]);
        }

        #pragma unroll
        for (int kb = 0; kb < 8; kb++) MMA_STEP(kb)

        if (pf) {
            #pragma unroll
            for (int k = 0; k < 4; k++) {
                uint32_t h01, h23, l01, l23;
                cvt_split4h(pa[k], pb[k], ms4, rs4, h01, h23, l01, l23);
                stsRow(nxtAh, nxtAl, rq + k * 8, h01, h23, l01, l23);
            }
            #pragma unroll
            for (int k = 0; k < 4; k++)
                gatherRow(nt * TR + rq + (k + 4) * 8, pa[k], pb[k]);
        }

        #pragma unroll
        for (int kb = 8; kb < 16; kb++) MMA_STEP(kb)

        if (pf) {
            #pragma unroll
            for (int k = 0; k < 4; k++) {
                uint32_t h01, h23, l01, l23;
                cvt_split4h(pa[k], pb[k], ms4, rs4, h01, h23, l01, l23);
                stsRow(nxtAh, nxtAl, rq + (k + 4) * 8, h01, h23, l01, l23);
            }
        }
        #undef MMA_STEP

        // ---- epilogue: +bias, store Y2, accumulate stats2 ----
        {
            const int g  = lane >> 2;
            const int e0 = t * TR + wm * 16 + g;
            const int e1 = e0 + 8;
            float* y0 = g_Y2 + (size_t)e0 * C2;
            float* y1 = g_Y2 + (size_t)e1 * C2;
            #pragma unroll
            for (int nb = 0; nb < 2; nb++) {
                const int c = wn * 16 + nb * 8 + tg * 2;
                const float bx = bias[nb * 2], by = bias[nb * 2 + 1];
                if (e0 < E) {
                    const float ox = acc[nb][0] + bx;
                    const float oy = acc[nb][1] + by;
                    *(float2*)(y0 + c) = make_float2(ox, oy);
                    sSum[nb * 2 + 0] += ox; sSq[nb * 2 + 0] += ox * ox;
                    sSum[nb * 2 + 1] += oy; sSq[nb * 2 + 1] += oy * oy;
                }
                if (e1 < E) {
                    const float ox = acc[nb][2] + bx;
                    const float oy = acc[nb][3] + by;
                    *(float2*)(y1 + c) = make_float2(ox, oy);
                    sSum[nb * 2 + 0] += ox; sSq[nb * 2 + 0] += ox * ox;
                    sSum[nb * 2 + 1] += oy; sSq[nb * 2 + 1] += oy * oy;
                }
            }
        }
        __syncthreads();
        cur ^= 1;
    }

    // ---- stats2 reduction: smem scratch, then global atomics ----
    float* sS = (float*)smraw;       // 64 floats
    float* sQ = sS + 64;             // 64 floats
    __syncthreads();
    if (tid < 128) sS[tid] = 0.f;
    __syncthreads();
    #pragma unroll
    for (int nb = 0; nb < 2; nb++) {
        const int c = wn * 16 + nb * 8 + tg * 2;
        atomicAdd(&sS[c],     sSum[nb * 2 + 0]);
        atomicAdd(&sS[c + 1], sSum[nb * 2 + 1]);
        atomicAdd(&sQ[c],     sSq[nb * 2 + 0]);
        atomicAdd(&sQ[c + 1], sSq[nb * 2 + 1]);
    }
    __syncthreads();
    if (tid < C2) {
        atomicAdd(&g_s2[tid],      sS[tid]);
        atomicAdd(&g_s2[C2 + tid], sQ[tid]);
    }
}

__global__ void k_fin2(float invE)
{
    const int c = threadIdx.x;
    if (c < C2) {
        const float m   = g_s2[c] * invE;
        const float var = g_s2[C2 + c] * invE - m * m;
        g_mr2[c]      = m;
        g_mr2[C2 + c] = rsqrtf(var + EPSV);
    }
}

// ================= layer 3: 2 edges/warp, float4 lanes =================
__global__ __launch_bounds__(256)
void k_out(const float* __restrict__ W3,
           const float* __restrict__ b3,
           float* __restrict__ out,
           int E)
{
    __shared__ float w[C2], m[C2], rs[C2];
    const int tid = threadIdx.x;
    if (tid < C2) {
        w[tid]  = W3[tid];
        m[tid]  = g_mr2[tid];
        rs[tid] = g_mr2[C2 + tid];
    }
    __syncthreads();

    const int lane = tid & 31;
    const int warp = tid >> 5;
    const int sub  = lane >> 4;           // 0/1: which edge in warp
    const int cq   = lane & 15;           // 4 channels each
    const int e = blockIdx.x * 16 + warp * 2 + sub;
    const bool valid = (e < E);

    float p = 0.0f;
    if (valid) {
        const float4 y = ((const float4*)(g_Y2 + (size_t)e * C2))[cq];
        const int c = cq * 4;
        p  = fmaxf(0.f, (y.x - m[c])     * rs[c])     * w[c];
        p += fmaxf(0.f, (y.y - m[c + 1]) * rs[c + 1]) * w[c + 1];
        p += fmaxf(0.f, (y.z - m[c + 2]) * rs[c + 2]) * w[c + 2];
        p += fmaxf(0.f, (y.w - m[c + 3]) * rs[c + 3]) * w[c + 3];
    }
    #pragma unroll
    for (int o = 8; o > 0; o >>= 1) p += __shfl_xor_sync(0xffffffffu, p, o);
    if (valid && cq == 0) out[e] = p + b3[0];
}

// ================= launch =================
extern "C" void kernel_launch(void* const* d_in, const int* in_sizes, int n_in,
                              void* d_out, int out_size)
{
    const float* emb = (const float*)d_in[0];
    const void*  ei  = d_in[1];
    const float* W1  = (const float*)d_in[2];
    const float* b1  = (const float*)d_in[3];
    const float* W2  = (const float*)d_in[4];
    const float* b2  = (const float*)d_in[5];
    const float* W3  = (const float*)d_in[6];
    const float* b3  = (const float*)d_in[7];
    float* out = (float*)d_out;

    const int N = in_sizes[0] / H;
    const int E = in_sizes[1] / 2;

    int dev = 0;
    cudaGetDevice(&dev);
    int nsm = 148;
    cudaDeviceGetAttribute(&nsm, cudaDevAttrMultiProcessorCount, dev);

    const int smP = (K1DIM * C1 + 32 * H) * (int)sizeof(float);   // 139264
    cudaFuncSetAttribute(k_proj,      cudaFuncAttributeMaxDynamicSharedMemorySize, smP);
    cudaFuncSetAttribute(k_gemm2_mma, cudaFuncAttributeMaxDynamicSharedMemorySize, SMT_G2);

    const int nTiles = (E + TR - 1) / TR;
    const int g2 = nsm < nTiles ? nsm : nTiles;

    k_pre<<<2, 256>>>((const int*)ei);
    k_proj<<<nsm, 256, smP>>>(emb, W1, b1, N);
    k_stats1<<<nsm * 8, 256>>>(ei, E);
    k_fin1<<<1, 256>>>(1.0f / (float)E);
    k_gemm2_mma<<<g2, 512, SMT_G2>>>(ei, W2, b2, E);
    k_fin2<<<1, 64>>>(1.0f / (float)E);
    k_out<<<(E + 15) / 16, 256>>>(W3, b3, out, E);
}

// round 11
// speedup vs baseline: 6.7237x; 1.1713x over previous
#include <cuda_runtime.h>
#include <cuda_bf16.h>
#include <cuda_fp16.h>
#include <cstdint>

#define NMAX 65536
#define EMAX 800000
#define K1DIM 128   // 2H
#define C1 256      // 4H
#define C2 64       // H
#define H  64
#define EPSV 1e-5f

// ---- warp MMA helpers (plain sm_103-compatible: no tcgen05) -------------
__device__ __forceinline__ uint32_t smem_u32(const void* p) {
    uint32_t a;
    asm("{ .reg .u64 t; cvta.to.shared.u64 t, %1; cvt.u32.u64 %0, t; }"
        : "=r"(a) : "l"(p));
    return a;
}
__device__ __forceinline__ void ldsm_x4(uint32_t& r0, uint32_t& r1,
                                        uint32_t& r2, uint32_t& r3, uint32_t addr) {
    asm volatile("ldmatrix.sync.aligned.m8n8.x4.shared.b16 {%0,%1,%2,%3}, [%4];"
                 : "=r"(r0), "=r"(r1), "=r"(r2), "=r"(r3) : "r"(addr));
}
__device__ __forceinline__ void ldsm_x4_t(uint32_t& r0, uint32_t& r1,
                                          uint32_t& r2, uint32_t& r3, uint32_t addr) {
    asm volatile("ldmatrix.sync.aligned.m8n8.x4.trans.shared.b16 {%0,%1,%2,%3}, [%4];"
                 : "=r"(r0), "=r"(r1), "=r"(r2), "=r"(r3) : "r"(addr));
}
__device__ __forceinline__ void mma16816h(float* d,
                                          uint32_t a0, uint32_t a1, uint32_t a2, uint32_t a3,
                                          uint32_t b0, uint32_t b1) {
    asm volatile("mma.sync.aligned.m16n8k16.row.col.f32.f16.f16.f32 "
                 "{%0,%1,%2,%3}, {%4,%5,%6,%7}, {%8,%9}, {%0,%1,%2,%3};"
                 : "+f"(d[0]), "+f"(d[1]), "+f"(d[2]), "+f"(d[3])
                 : "r"(a0), "r"(a1), "r"(a2), "r"(a3), "r"(b0), "r"(b1));
}

// ================= scratch =================
__device__ float    g_Pt[(size_t)NMAX * C1];     // fp32 planes (gemm2)
__device__ float    g_Pb[(size_t)NMAX * C1];
__device__ uint32_t g_PtH[(size_t)NMAX * 128];   // bf16x2 planes (stats1)
__device__ uint32_t g_PbH[(size_t)NMAX * 128];
__device__ uint32_t g_Y2h[(size_t)EMAX * 32];    // fp16x2 layer-2 output
__device__ float    g_s1[2 * C1];
__device__ float    g_mr1[2 * C1];
__device__ float    g_s2[2 * C2];
__device__ float    g_mr2[2 * C2];
__device__ int      g_idx64;

// ================= pre =================
__global__ void k_pre(const int* __restrict__ ei_words)
{
    int gid = blockIdx.x * blockDim.x + threadIdx.x;
    if (gid == 0) {
        int orv = 0;
        #pragma unroll
        for (int i = 1; i < 32; i += 2) orv |= ei_words[i];
        g_idx64 = (orv == 0) ? 1 : 0;
    }
    if (gid < 2 * C1) g_s1[gid] = 0.0f;
    if (gid < 2 * C2) g_s2[gid] = 0.0f;
}

// ================= node projection (fp32 SIMT) =================
__global__ __launch_bounds__(256, 1)
void k_proj(const float* __restrict__ emb,
            const float* __restrict__ W1,
            const float* __restrict__ b1,
            int N)
{
    extern __shared__ float sm[];
    float* Ws = sm;                 // 128*256
    float* As = sm + K1DIM * C1;    // 32*64

    const int tid = threadIdx.x;
    for (int i = tid; i < K1DIM * C1 / 4; i += blockDim.x)
        ((float4*)Ws)[i] = ((const float4*)W1)[i];

    const int tx = tid & 31;
    const int ty = tid >> 5;

    float biasReg[8];
    #pragma unroll
    for (int c = 0; c < 8; c++) biasReg[c] = b1[tx * 8 + c];

    __syncthreads();

    const int nTiles = (N + 31) / 32;
    for (int tile = blockIdx.x; tile < nTiles; tile += gridDim.x) {
        const int base = tile * 32;
        for (int i = tid; i < 32 * 16; i += blockDim.x) {
            const int r = i >> 4, q = i & 15;
            const int n = base + r;
            float4 v = make_float4(0.f, 0.f, 0.f, 0.f);
            if (n < N) v = ((const float4*)(emb + (size_t)n * H))[q];
            ((float4*)(As + r * H))[q] = v;
        }
        __syncthreads();

        const float* Arow = As + (ty * 4) * H;

        #define PROJ_PASS(ROWOFF, DST, DSTH, ADDBIAS)                         \
        {                                                                     \
            float acc[4][8];                                                  \
            _Pragma("unroll")                                                 \
            for (int r = 0; r < 4; r++)                                       \
                _Pragma("unroll")                                             \
                for (int c = 0; c < 8; c++) acc[r][c] = 0.0f;                 \
            _Pragma("unroll 4")                                               \
            for (int k = 0; k < H; k++) {                                     \
                const float4 w0 = *((const float4*)(Ws + (ROWOFF + k) * C1 + tx * 8));     \
                const float4 w1 = *((const float4*)(Ws + (ROWOFF + k) * C1 + tx * 8 + 4)); \
                const float a0 = Arow[k];                                     \
                const float a1 = Arow[H + k];                                 \
                const float a2 = Arow[2 * H + k];                             \
                const float a3 = Arow[3 * H + k];                             \
                _Pragma("unroll")                                             \
                for (int r = 0; r < 4; r++) {                                 \
                    const float a = (r == 0) ? a0 : (r == 1) ? a1 : (r == 2) ? a2 : a3; \
                    acc[r][0] += a * w0.x; acc[r][1] += a * w0.y;             \
                    acc[r][2] += a * w0.z; acc[r][3] += a * w0.w;             \
                    acc[r][4] += a * w1.x; acc[r][5] += a * w1.y;             \
                    acc[r][6] += a * w1.z; acc[r][7] += a * w1.w;             \
                }                                                             \
            }                                                                 \
            _Pragma("unroll")                                                 \
            for (int r = 0; r < 4; r++) {                                     \
                const int n = base + ty * 4 + r;                              \
                if (n < N) {                                                  \
                    float v[8];                                               \
                    _Pragma("unroll")                                         \
                    for (int c = 0; c < 8; c++)                               \
                        v[c] = acc[r][c] + (ADDBIAS ? biasReg[c] : 0.0f);     \
                    float4* dst = (float4*)(DST + (size_t)n * C1 + tx * 8);   \
                    dst[0] = make_float4(v[0], v[1], v[2], v[3]);             \
                    dst[1] = make_float4(v[4], v[5], v[6], v[7]);             \
                    const __nv_bfloat162 p01 = __floats2bfloat162_rn(v[0], v[1]); \
                    const __nv_bfloat162 p23 = __floats2bfloat162_rn(v[2], v[3]); \
                    const __nv_bfloat162 p45 = __floats2bfloat162_rn(v[4], v[5]); \
                    const __nv_bfloat162 p67 = __floats2bfloat162_rn(v[6], v[7]); \
                    uint4 u;                                                  \
                    u.x = *(const uint32_t*)&p01; u.y = *(const uint32_t*)&p23; \
                    u.z = *(const uint32_t*)&p45; u.w = *(const uint32_t*)&p67; \
                    ((uint4*)(DSTH + (size_t)n * 128))[tx] = u;               \
                }                                                             \
            }                                                                 \
        }
        PROJ_PASS(0,  g_Pt, g_PtH, 1)
        PROJ_PASS(64, g_Pb, g_PbH, 0)
        #undef PROJ_PASS
        __syncthreads();
    }
}

// ================= layer-1 stats (bf16 planes, half traffic) =============
__global__ __launch_bounds__(256)
void k_stats1(const void* __restrict__ ei, int E)
{
    const long long* ei64 = (const long long*)ei;
    const int*       ei32 = (const int*)ei;
    const int is64 = g_idx64;
    const int c2   = threadIdx.x & 127;
    const int half = threadIdx.x >> 7;

    float s0 = 0.f, q0 = 0.f, s1 = 0.f, q1 = 0.f;
    const int stride = gridDim.x * 8;
    for (int e0 = blockIdx.x * 8 + half * 4; e0 < E; e0 += stride) {
        uint32_t ta[4], tb[4];
        int nv = 0;
        #pragma unroll
        for (int j = 0; j < 4; j++) {
            const int e = e0 + j;
            if (e < E) {
                const long long ci = is64 ? ei64[e]     : (long long)ei32[e];
                const long long ri = is64 ? ei64[E + e] : (long long)ei32[E + e];
                ta[j] = __ldg(g_PtH + ci * 128 + c2);
                tb[j] = __ldg(g_PbH + ri * 128 + c2);
                nv = j + 1;
            }
        }
        #pragma unroll
        for (int j = 0; j < 4; j++) {
            if (j < nv) {
                const float2 af = __bfloat1622float2(*(const __nv_bfloat162*)&ta[j]);
                const float2 bf = __bfloat1622float2(*(const __nv_bfloat162*)&tb[j]);
                const float v0 = af.x + bf.x;
                const float v1 = af.y + bf.y;
                s0 += v0; q0 += v0 * v0;
                s1 += v1; q1 += v1 * v1;
            }
        }
    }
    atomicAdd(&g_s1[2 * c2],          s0);
    atomicAdd(&g_s1[2 * c2 + 1],      s1);
    atomicAdd(&g_s1[C1 + 2 * c2],     q0);
    atomicAdd(&g_s1[C1 + 2 * c2 + 1], q1);
}

__global__ void k_fin1(float invE)
{
    const int c = threadIdx.x;
    if (c < C1) {
        const float m   = g_s1[c] * invE;
        const float var = g_s1[C1 + c] * invE - m * m;
        g_mr1[c]      = m;
        g_mr1[C1 + c] = rsqrtf(var + EPSV);
    }
}

// ================= layer 2: pipelined single-plane fp16 MMA ==============
// 512 threads = 16 warps. Tile = 128 edges x 64 cols, K = 256, double-
// buffered fp16 A plane, single fp16 B plane (W2^T).
// Warp: wm = wid&7 -> rows [wm*16,+16); wn = wid>>3 -> cols [wn*32,+32).
#define TR 128
#define ASTR 264               // A smem row stride (fp16), 8-elem pad
#define BSTR 72                // B smem row stride (fp16), 8-elem pad
#define ABUF (TR * ASTR * 2)   // 67584 B per buffer
#define BPLANE (C1 * BSTR * 2) // 36864 B
#define OFF_B (2 * ABUF)       // 135168
#define SMT_G2 (OFF_B + BPLANE)   // 172032

__device__ __forceinline__ void cvt4h(float4 a, float4 b, float4 ms, float4 rs,
                                      uint32_t& h01, uint32_t& h23)
{
    const float v0 = fmaxf(0.f, (a.x + b.x - ms.x) * rs.x);
    const float v1 = fmaxf(0.f, (a.y + b.y - ms.y) * rs.y);
    const float v2 = fmaxf(0.f, (a.z + b.z - ms.z) * rs.z);
    const float v3 = fmaxf(0.f, (a.w + b.w - ms.w) * rs.w);
    const __half2 H01 = __floats2half2_rn(v0, v1);
    const __half2 H23 = __floats2half2_rn(v2, v3);
    h01 = *(const uint32_t*)&H01; h23 = *(const uint32_t*)&H23;
}

__global__ __launch_bounds__(512, 1)
void k_gemm2_mma(const void* __restrict__ ei,
                 const float* __restrict__ W2,
                 const float* __restrict__ b2,
                 int E)
{
    extern __shared__ char smraw[];
    const uint32_t smBase = smem_u32(smraw);
    __half* Bh = (__half*)(smraw + OFF_B);
    const uint32_t BhA = smBase + OFF_B;

    const int tid  = threadIdx.x;
    const int lane = tid & 31;
    const int wid  = tid >> 5;

    // --- build W2^T fp16 plane ---
    for (int i = tid; i < C1 * C2; i += 512) {
        const int k = i >> 6, n = i & 63;
        Bh[k * BSTR + n] = __float2half(W2[k * C2 + n]);
    }

    const long long* ei64 = (const long long*)ei;
    const int*       ei32 = (const int*)ei;
    const int is64 = g_idx64;

    // loop-invariant per-thread normalization params (q = tid&63 fixed)
    const int q  = tid & 63;
    const int rq = tid >> 6;                 // base row 0..7; rows rq + j*8
    const float4 ms4 = ((const float4*)g_mr1)[q];
    const float4 rs4 = ((const float4*)(g_mr1 + C1))[q];

    const int wm = wid & 7;          // row group (16 rows)
    const int wn = wid >> 3;         // col group (32 cols)
    const int tg = lane & 3;
    const uint32_t aOff = (uint32_t)((wm * 16 + (lane & 15)) * ASTR + (lane >> 4) * 8) * 2;
    const uint32_t bOff = (uint32_t)(((lane & 7) + ((lane >> 3) & 1) * 8) * BSTR
                                     + wn * 32 + (lane >> 4) * 8) * 2;

    float bias[8];
    #pragma unroll
    for (int nb = 0; nb < 4; nb++) {
        bias[nb * 2 + 0] = b2[wn * 32 + nb * 8 + tg * 2];
        bias[nb * 2 + 1] = b2[wn * 32 + nb * 8 + tg * 2 + 1];
    }

    float sSum[8], sSq[8];
    #pragma unroll
    for (int i = 0; i < 8; i++) { sSum[i] = 0.f; sSq[i] = 0.f; }

    const int nTiles = (E + TR - 1) / TR;
    const int stride = gridDim.x;

    auto gatherRow = [&](int e, float4& a, float4& b) {
        a = make_float4(0.f, 0.f, 0.f, 0.f);
        b = make_float4(0.f, 0.f, 0.f, 0.f);
        if (e < E) {
            const long long ci = is64 ? ei64[e]     : (long long)ei32[e];
            const long long ri = is64 ? ei64[E + e] : (long long)ei32[E + e];
            a = ((const float4*)(g_Pt + ci * C1))[q];
            b = ((const float4*)(g_Pb + ri * C1))[q];
        }
    };
    auto stsRow = [&](char* bA, int r, uint32_t h01, uint32_t h23) {
        uint32_t* ah = (uint32_t*)(bA + r * (ASTR * 2));
        ah[q * 2] = h01; ah[q * 2 + 1] = h23;
    };

    // prologue: full build of first tile into buffer 0 (16 rows/thread)
    if (blockIdx.x < nTiles) {
        #pragma unroll
        for (int j = 0; j < 16; j++) {
            const int r = rq + j * 8;
            float4 a, b;
            gatherRow(blockIdx.x * TR + r, a, b);
            uint32_t h01, h23;
            cvt4h(a, b, ms4, rs4, h01, h23);
            stsRow(smraw, r, h01, h23);
        }
    }
    __syncthreads();

    int cur = 0;
    for (int t = blockIdx.x; t < nTiles; t += stride) {
        const int nt = t + stride;
        const bool pf = (nt < nTiles);
        const uint32_t curA = smBase + cur * ABUF;
        char* nxtA = smraw + (cur ^ 1) * ABUF;

        float acc[4][4];
        #pragma unroll
        for (int nb = 0; nb < 4; nb++)
            #pragma unroll
            for (int c = 0; c < 4; c++) acc[nb][c] = 0.0f;

        #define MMA_STEP(kb)                                                  \
        {                                                                     \
            uint32_t a0, a1, a2, a3, b0, b1, b2_, b3_, c0, c1, c2_, c3_;      \
            ldsm_x4(a0, a1, a2, a3, curA + aOff + (kb) * 32);                 \
            const uint32_t bk = BhA + bOff + (kb) * (16 * BSTR * 2);          \
            ldsm_x4_t(b0, b1, b2_, b3_, bk);                                  \
            ldsm_x4_t(c0, c1, c2_, c3_, bk + 32);                             \
            mma16816h(acc[0], a0, a1, a2, a3, b0, b1);                        \
            mma16816h(acc[1], a0, a1, a2, a3, b2_, b3_);                      \
            mma16816h(acc[2], a0, a1, a2, a3, c0, c1);                        \
            mma16816h(acc[3], a0, a1, a2, a3, c2_, c3_);                      \
        }

        float4 pa[4], pb[4];
        #define GATHER_G(g)                                                   \
            _Pragma("unroll")                                                 \
            for (int k = 0; k < 4; k++)                                       \
                gatherRow(nt * TR + rq + ((g) * 4 + k) * 8, pa[k], pb[k]);
        #define STS_G(g)                                                      \
            _Pragma("unroll")                                                 \
            for (int k = 0; k < 4; k++) {                                     \
                uint32_t h01, h23;                                            \
                cvt4h(pa[k], pb[k], ms4, rs4, h01, h23);                      \
                stsRow(nxtA, rq + ((g) * 4 + k) * 8, h01, h23);               \
            }

        if (pf) { GATHER_G(0) }
        MMA_STEP(0) MMA_STEP(1) MMA_STEP(2) MMA_STEP(3)
        if (pf) { STS_G(0) GATHER_G(1) }
        MMA_STEP(4) MMA_STEP(5) MMA_STEP(6) MMA_STEP(7)
        if (pf) { STS_G(1) GATHER_G(2) }
        MMA_STEP(8) MMA_STEP(9) MMA_STEP(10) MMA_STEP(11)
        if (pf) { STS_G(2) GATHER_G(3) }
        MMA_STEP(12) MMA_STEP(13) MMA_STEP(14) MMA_STEP(15)
        if (pf) { STS_G(3) }

        #undef MMA_STEP
        #undef GATHER_G
        #undef STS_G

        // ---- epilogue: +bias, store Y2 (fp16x2), accumulate stats2 ----
        {
            const int g_  = lane >> 2;
            const int e0 = t * TR + wm * 16 + g_;
            const int e1 = e0 + 8;
            #pragma unroll
            for (int nb = 0; nb < 4; nb++) {
                const int c = wn * 32 + nb * 8 + tg * 2;
                const float bx = bias[nb * 2], by = bias[nb * 2 + 1];
                if (e0 < E) {
                    const float ox = acc[nb][0] + bx;
                    const float oy = acc[nb][1] + by;
                    const __half2 h = __floats2half2_rn(ox, oy);
                    g_Y2h[(size_t)e0 * 32 + (c >> 1)] = *(const uint32_t*)&h;
                    sSum[nb * 2 + 0] += ox; sSq[nb * 2 + 0] += ox * ox;
                    sSum[nb * 2 + 1] += oy; sSq[nb * 2 + 1] += oy * oy;
                }
                if (e1 < E) {
                    const float ox = acc[nb][2] + bx;
                    const float oy = acc[nb][3] + by;
                    const __half2 h = __floats2half2_rn(ox, oy);
                    g_Y2h[(size_t)e1 * 32 + (c >> 1)] = *(const uint32_t*)&h;
                    sSum[nb * 2 + 0] += ox; sSq[nb * 2 + 0] += ox * ox;
                    sSum[nb * 2 + 1] += oy; sSq[nb * 2 + 1] += oy * oy;
                }
            }
        }
        __syncthreads();
        cur ^= 1;
    }

    // ---- stats2 reduction: smem scratch, then global atomics ----
    float* sS = (float*)smraw;       // 64 floats
    float* sQ = sS + 64;             // 64 floats
    __syncthreads();
    if (tid < 128) sS[tid] = 0.f;
    __syncthreads();
    #pragma unroll
    for (int nb = 0; nb < 4; nb++) {
        const int c = wn * 32 + nb * 8 + tg * 2;
        atomicAdd(&sS[c],     sSum[nb * 2 + 0]);
        atomicAdd(&sS[c + 1], sSum[nb * 2 + 1]);
        atomicAdd(&sQ[c],     sSq[nb * 2 + 0]);
        atomicAdd(&sQ[c + 1], sSq[nb * 2 + 1]);
    }
    __syncthreads();
    if (tid < C2) {
        atomicAdd(&g_s2[tid],      sS[tid]);
        atomicAdd(&g_s2[C2 + tid], sQ[tid]);
    }
}

__global__ void k_fin2(float invE)
{
    const int c = threadIdx.x;
    if (c < C2) {
        const float m   = g_s2[c] * invE;
        const float var = g_s2[C2 + c] * invE - m * m;
        g_mr2[c]      = m;
        g_mr2[C2 + c] = rsqrtf(var + EPSV);
    }
}

// ================= layer 3: 2 edges/warp, fp16 Y2 reads =================
__global__ __launch_bounds__(256)
void k_out(const float* __restrict__ W3,
           const float* __restrict__ b3,
           float* __restrict__ out,
           int E)
{
    __shared__ float w[C2], m[C2], rs[C2];
    const int tid = threadIdx.x;
    if (tid < C2) {
        w[tid]  = W3[tid];
        m[tid]  = g_mr2[tid];
        rs[tid] = g_mr2[C2 + tid];
    }
    __syncthreads();

    const int lane = tid & 31;
    const int warp = tid >> 5;
    const int sub  = lane >> 4;           // 0/1: which edge in warp
    const int cq   = lane & 15;           // 4 channels each
    const int e = blockIdx.x * 16 + warp * 2 + sub;
    const bool valid = (e < E);

    float p = 0.0f;
    if (valid) {
        const uint2 u = ((const uint2*)(g_Y2h + (size_t)e * 32))[cq];
        const float2 y01 = __half22float2(*(const __half2*)&u.x);
        const float2 y23 = __half22float2(*(const __half2*)&u.y);
        const int c = cq * 4;
        p  = fmaxf(0.f, (y01.x - m[c])     * rs[c])     * w[c];
        p += fmaxf(0.f, (y01.y - m[c + 1]) * rs[c + 1]) * w[c + 1];
        p += fmaxf(0.f, (y23.x - m[c + 2]) * rs[c + 2]) * w[c + 2];
        p += fmaxf(0.f, (y23.y - m[c + 3]) * rs[c + 3]) * w[c + 3];
    }
    #pragma unroll
    for (int o = 8; o > 0; o >>= 1) p += __shfl_xor_sync(0xffffffffu, p, o);
    if (valid && cq == 0) out[e] = p + b3[0];
}

// ================= launch =================
extern "C" void kernel_launch(void* const* d_in, const int* in_sizes, int n_in,
                              void* d_out, int out_size)
{
    const float* emb = (const float*)d_in[0];
    const void*  ei  = d_in[1];
    const float* W1  = (const float*)d_in[2];
    const float* b1  = (const float*)d_in[3];
    const float* W2  = (const float*)d_in[4];
    const float* b2  = (const float*)d_in[5];
    const float* W3  = (const float*)d_in[6];
    const float* b3  = (const float*)d_in[7];
    float* out = (float*)d_out;

    const int N = in_sizes[0] / H;
    const int E = in_sizes[1] / 2;

    int dev = 0;
    cudaGetDevice(&dev);
    int nsm = 148;
    cudaDeviceGetAttribute(&nsm, cudaDevAttrMultiProcessorCount, dev);

    const int smP = (K1DIM * C1 + 32 * H) * (int)sizeof(float);   // 139264
    cudaFuncSetAttribute(k_proj,      cudaFuncAttributeMaxDynamicSharedMemorySize, smP);
    cudaFuncSetAttribute(k_gemm2_mma, cudaFuncAttributeMaxDynamicSharedMemorySize, SMT_G2);

    const int nTiles = (E + TR - 1) / TR;
    const int g2 = nsm < nTiles ? nsm : nTiles;

    k_pre<<<2, 256>>>((const int*)ei);
    k_proj<<<nsm, 256, smP>>>(emb, W1, b1, N);
    k_stats1<<<nsm * 8, 256>>>(ei, E);
    k_fin1<<<1, 256>>>(1.0f / (float)E);
    k_gemm2_mma<<<g2, 512, SMT_G2>>>(ei, W2, b2, E);
    k_fin2<<<1, 64>>>(1.0f / (float)E);
    k_out<<<(E + 15) / 16, 256>>>(W3, b3, out, E);
}